// round 1
// baseline (speedup 1.0000x reference)
#include <cuda_runtime.h>

#define NN 200000
#define NE 400000
#define NG 64
#define HD 128
#define IND 5

// Scratch (allocation-free rule: __device__ globals)
__device__ float g_h[NN * HD];      // x + aggr accumulator (layer input + scatter target)
__device__ float g_bufA[NN * HD];   // layer outputs ping
__device__ float g_bufB[NN * HD];   // layer outputs pong
__device__ float g_pool[NG * HD];
__device__ int   g_cnt[NG];

// ---------------------------------------------------------------------------
__global__ void copy_f(float* __restrict__ dst, const float* __restrict__ src, int n) {
    int i = blockIdx.x * blockDim.x + threadIdx.x;
    if (i < n) dst[i] = src[i];
}

__global__ void copy_f4(float4* __restrict__ dst, const float4* __restrict__ src, int n4) {
    int i = blockIdx.x * blockDim.x + threadIdx.x;
    if (i < n4) dst[i] = src[i];
}

// ---------------------------------------------------------------------------
// Edge message + scatter for din=5 (layer 0). One thread per edge.
__global__ void edge5(const int* __restrict__ src, const int* __restrict__ dst,
                      const float* __restrict__ ea,
                      const float* __restrict__ ew, const float* __restrict__ eb,
                      const float* __restrict__ x, float* __restrict__ h) {
    int e = blockIdx.x * blockDim.x + threadIdx.x;
    if (e >= NE) return;
    int s = src[e], d = dst[e];
    float a = ea[e];
#pragma unroll
    for (int j = 0; j < IND; j++) {
        float m = fmaxf(x[s * IND + j] + fmaf(a, ew[j], eb[j]), 0.f);
        atomicAdd(&h[d * IND + j], m);
    }
}

// Edge message + scatter for din=128. 32 threads (1 warp-row) per edge, float4 cols.
__global__ void edge128(const int* __restrict__ src, const int* __restrict__ dst,
                        const float* __restrict__ ea,
                        const float* __restrict__ ew, const float* __restrict__ eb,
                        const float* __restrict__ x, float* __restrict__ h) {
    int t = blockIdx.x * blockDim.x + threadIdx.x;
    int e = t >> 5;
    if (e >= NE) return;
    int lane = t & 31;
    int s = src[e], d = dst[e];
    float a = ea[e];
    int c = lane * 4;
    float4 xv = *(const float4*)(x + (size_t)s * HD + c);
    float4 wv = *(const float4*)(ew + c);
    float4 bv = *(const float4*)(eb + c);
    float m0 = fmaxf(xv.x + fmaf(a, wv.x, bv.x), 0.f);
    float m1 = fmaxf(xv.y + fmaf(a, wv.y, bv.y), 0.f);
    float m2 = fmaxf(xv.z + fmaf(a, wv.z, bv.z), 0.f);
    float m3 = fmaxf(xv.w + fmaf(a, wv.w, bv.w), 0.f);
    float* p = h + (size_t)d * HD + c;
    atomicAdd(p + 0, m0);
    atomicAdd(p + 1, m1);
    atomicAdd(p + 2, m2);
    atomicAdd(p + 3, m3);
}

// ---------------------------------------------------------------------------
// Fused MLP + LayerNorm + ReLU for a 64-node tile.
// 256 threads: ty = warp (0..7) owns 8 rows, tx = lane owns 4 output cols.
// NN % 64 == 0 so no bounds checks.
template <int DIN>
__global__ void __launch_bounds__(256) mlp_ln(
        const float* __restrict__ h,
        const float* __restrict__ w1, const float* __restrict__ b1,
        const float* __restrict__ w2, const float* __restrict__ b2,
        const float* __restrict__ gam, const float* __restrict__ bet,
        float* __restrict__ out) {
    __shared__ float s_in[64][DIN + 4];
    __shared__ float s_mid[64][HD + 4];

    int tid = threadIdx.x;
    int tx = tid & 31, ty = tid >> 5;
    int n0 = blockIdx.x * 64;
    int cb = tx * 4;

    // --- load input tile (h = x + aggr already) ---
    if (DIN == HD) {
        const float4* srcp = (const float4*)(h + (size_t)n0 * DIN);
        for (int i = tid; i < 64 * DIN / 4; i += 256) {
            float4 v = srcp[i];
            int r = i >> 5;
            int c = (i & 31) * 4;
            s_in[r][c + 0] = v.x; s_in[r][c + 1] = v.y;
            s_in[r][c + 2] = v.z; s_in[r][c + 3] = v.w;
        }
    } else {
        for (int i = tid; i < 64 * DIN; i += 256)
            s_in[i / DIN][i % DIN] = h[(size_t)n0 * DIN + i];
    }
    __syncthreads();

    // --- GEMM1: [64,DIN] @ [DIN,128] ---
    float acc[8][4];
#pragma unroll
    for (int r = 0; r < 8; r++)
#pragma unroll
        for (int c = 0; c < 4; c++) acc[r][c] = 0.f;

    for (int k = 0; k < DIN; k++) {
        float4 w = *(const float4*)(w1 + (size_t)k * HD + cb);
#pragma unroll
        for (int r = 0; r < 8; r++) {
            float a = s_in[ty * 8 + r][k];
            acc[r][0] = fmaf(a, w.x, acc[r][0]);
            acc[r][1] = fmaf(a, w.y, acc[r][1]);
            acc[r][2] = fmaf(a, w.z, acc[r][2]);
            acc[r][3] = fmaf(a, w.w, acc[r][3]);
        }
    }
    {
        float4 bb = *(const float4*)(b1 + cb);
#pragma unroll
        for (int r = 0; r < 8; r++) {
            int rr = ty * 8 + r;
            s_mid[rr][cb + 0] = fmaxf(acc[r][0] + bb.x, 0.f);
            s_mid[rr][cb + 1] = fmaxf(acc[r][1] + bb.y, 0.f);
            s_mid[rr][cb + 2] = fmaxf(acc[r][2] + bb.z, 0.f);
            s_mid[rr][cb + 3] = fmaxf(acc[r][3] + bb.w, 0.f);
        }
    }
    __syncthreads();

    // --- GEMM2: [64,128] @ [128,128] ---
    float acc2[8][4];
#pragma unroll
    for (int r = 0; r < 8; r++)
#pragma unroll
        for (int c = 0; c < 4; c++) acc2[r][c] = 0.f;

    for (int k = 0; k < HD; k++) {
        float4 w = *(const float4*)(w2 + (size_t)k * HD + cb);
#pragma unroll
        for (int r = 0; r < 8; r++) {
            float a = s_mid[ty * 8 + r][k];
            acc2[r][0] = fmaf(a, w.x, acc2[r][0]);
            acc2[r][1] = fmaf(a, w.y, acc2[r][1]);
            acc2[r][2] = fmaf(a, w.z, acc2[r][2]);
            acc2[r][3] = fmaf(a, w.w, acc2[r][3]);
        }
    }

    // --- bias2 + LayerNorm + ReLU ---
    float4 bb2 = *(const float4*)(b2 + cb);
    float4 gv  = *(const float4*)(gam + cb);
    float4 bv  = *(const float4*)(bet + cb);
#pragma unroll
    for (int r = 0; r < 8; r++) {
        float v0 = acc2[r][0] + bb2.x;
        float v1 = acc2[r][1] + bb2.y;
        float v2 = acc2[r][2] + bb2.z;
        float v3 = acc2[r][3] + bb2.w;
        float s  = v0 + v1 + v2 + v3;
        float s2 = v0 * v0 + v1 * v1 + v2 * v2 + v3 * v3;
#pragma unroll
        for (int o = 16; o > 0; o >>= 1) {
            s  += __shfl_xor_sync(0xffffffffu, s, o);
            s2 += __shfl_xor_sync(0xffffffffu, s2, o);
        }
        float mean = s * (1.f / HD);
        float var  = s2 * (1.f / HD) - mean * mean;
        float rstd = rsqrtf(var + 1e-5f);
        float4 o4;
        o4.x = fmaxf((v0 - mean) * rstd * gv.x + bv.x, 0.f);
        o4.y = fmaxf((v1 - mean) * rstd * gv.y + bv.y, 0.f);
        o4.z = fmaxf((v2 - mean) * rstd * gv.z + bv.z, 0.f);
        o4.w = fmaxf((v3 - mean) * rstd * gv.w + bv.w, 0.f);
        *(float4*)(out + (size_t)(n0 + ty * 8 + r) * HD + cb) = o4;
    }
}

// ---------------------------------------------------------------------------
__global__ void zero_pool() {
    int i = blockIdx.x * blockDim.x + threadIdx.x;
    if (i < NG * HD) g_pool[i] = 0.f;
    if (i < NG) g_cnt[i] = 0;
}

// batch is sorted: per-block segmented running sum, atomics only at boundaries.
__global__ void pool128(const float* __restrict__ x, const int* __restrict__ batch) {
    const int CHUNK = 200;                  // 1000 blocks * 200 = 200000
    int n0 = blockIdx.x * CHUNK;
    int n1 = n0 + CHUNK;
    if (n1 > NN) n1 = NN;
    int j = threadIdx.x;                    // 128 threads = cols
    float acc = 0.f;
    int cnt = 0;
    int cur = batch[n0];
    for (int n = n0; n < n1; n++) {
        int g = batch[n];
        if (g != cur) {
            atomicAdd(&g_pool[cur * HD + j], acc);
            if (j == 0) atomicAdd(&g_cnt[cur], cnt);
            acc = 0.f; cnt = 0; cur = g;
        }
        acc += x[(size_t)n * HD + j];
        cnt++;
    }
    atomicAdd(&g_pool[cur * HD + j], acc);
    if (j == 0) atomicAdd(&g_cnt[cur], cnt);
}

__global__ void finalize(float* __restrict__ out) {
    int g = blockIdx.x, j = threadIdx.x;
    float s = g_pool[g * HD + j];
    int c = g_cnt[g];
    float cf = (float)(c > 1 ? c : 1);
    out[g * 2 * HD + j]      = s / cf;
    out[g * 2 * HD + HD + j] = s;
}

// ---------------------------------------------------------------------------
extern "C" void kernel_launch(void* const* d_in, const int* in_sizes, int n_in,
                              void* d_out, int out_size) {
    const float* x     = (const float*)d_in[0];
    const int*   ei    = (const int*)d_in[1];
    const float* ea    = (const float*)d_in[2];
    const int*   batch = (const int*)d_in[3];
    const float* P[24];
    for (int i = 0; i < 24; i++) P[i] = (const float*)d_in[4 + i];
    const int* esrc = ei;
    const int* edst = ei + NE;

    float *h, *bufA, *bufB;
    cudaGetSymbolAddress((void**)&h, g_h);
    cudaGetSymbolAddress((void**)&bufA, g_bufA);
    cudaGetSymbolAddress((void**)&bufB, g_bufB);

    const int TB = 256;

    // ---- layer 0 (din = 5) ----
    copy_f<<<(NN * IND + TB - 1) / TB, TB>>>(h, x, NN * IND);
    edge5<<<(NE + TB - 1) / TB, TB>>>(esrc, edst, ea, P[0], P[1], x, h);
    mlp_ln<IND><<<NN / 64, 256>>>(h, P[2], P[3], P[4], P[5], P[6], P[7], bufA);

    // ---- layer 1 (din = 128) ----
    copy_f4<<<(NN * HD / 4 + TB - 1) / TB, TB>>>((float4*)h, (const float4*)bufA, NN * HD / 4);
    edge128<<<(NE * 32 + TB - 1) / TB, TB>>>(esrc, edst, ea, P[8], P[9], bufA, h);
    mlp_ln<HD><<<NN / 64, 256>>>(h, P[10], P[11], P[12], P[13], P[14], P[15], bufB);

    // ---- layer 2 (din = 128) ----
    copy_f4<<<(NN * HD / 4 + TB - 1) / TB, TB>>>((float4*)h, (const float4*)bufB, NN * HD / 4);
    edge128<<<(NE * 32 + TB - 1) / TB, TB>>>(esrc, edst, ea, P[16], P[17], bufB, h);
    mlp_ln<HD><<<NN / 64, 256>>>(h, P[18], P[19], P[20], P[21], P[22], P[23], bufA);

    // ---- pooling ----
    zero_pool<<<(NG * HD + TB - 1) / TB, TB>>>();
    pool128<<<NN / 200, HD>>>(bufA, batch);
    finalize<<<NG, HD>>>((float*)d_out);
}

// round 2
// speedup vs baseline: 1.4165x; 1.4165x over previous
#include <cuda_runtime.h>

#define NN 200000
#define NE 400000
#define NG 64
#define HD 128
#define IND 5
#define LDT 66   // transposed smem row stride in floats (8B-aligned, odd-ish banks)

// Scratch (allocation-free rule: __device__ globals)
__device__ float g_h5[NN * IND];    // layer-0 accumulation base (x + aggr), 5-dim
__device__ float g_h[NN * HD];      // layer-1/2 accumulation base (y + aggr)
__device__ float g_bufA[NN * HD];   // layer outputs ping
__device__ float g_bufB[NN * HD];   // layer outputs pong
__device__ float g_pool[NG * HD];
__device__ int   g_cnt[NG];

// ---------------------------------------------------------------------------
// Packed dual-FMA: d.x += a.x*b.x ; d.y += a.y*b.y  (single FFMA2 instruction)
__device__ __forceinline__ void ffma2(float2 &d, const float2 &a, const float2 &b) {
    asm("fma.rn.f32x2 %0, %1, %2, %0;"
        : "+l"(reinterpret_cast<unsigned long long &>(d))
        : "l"(reinterpret_cast<const unsigned long long &>(a)),
          "l"(reinterpret_cast<const unsigned long long &>(b)));
}

// ---------------------------------------------------------------------------
__global__ void copy_f(float* __restrict__ dst, const float* __restrict__ src, int n) {
    int i = blockIdx.x * blockDim.x + threadIdx.x;
    if (i < n) dst[i] = src[i];
}

// ---------------------------------------------------------------------------
// Edge message + scatter for din=5 (layer 0). One thread per edge.
__global__ void edge5(const int* __restrict__ src, const int* __restrict__ dst,
                      const float* __restrict__ ea,
                      const float* __restrict__ ew, const float* __restrict__ eb,
                      const float* __restrict__ x, float* __restrict__ h) {
    int e = blockIdx.x * blockDim.x + threadIdx.x;
    if (e >= NE) return;
    int s = __ldg(src + e), d = __ldg(dst + e);
    float a = __ldg(ea + e);
#pragma unroll
    for (int j = 0; j < IND; j++) {
        float m = fmaxf(__ldg(x + s * IND + j) + fmaf(a, __ldg(ew + j), __ldg(eb + j)), 0.f);
        atomicAdd(&h[d * IND + j], m);
    }
}

// Edge message + scatter for din=128. 1 warp per edge, float4 per lane, vector RED.
__global__ void edge128(const int* __restrict__ src, const int* __restrict__ dst,
                        const float* __restrict__ ea,
                        const float* __restrict__ ew, const float* __restrict__ eb,
                        const float* __restrict__ x, float* __restrict__ h) {
    int t = blockIdx.x * blockDim.x + threadIdx.x;
    int e = t >> 5;
    if (e >= NE) return;
    int lane = t & 31;
    int s = __ldg(src + e), d = __ldg(dst + e);
    float a = __ldg(ea + e);
    float4 xv = __ldg((const float4*)(x + (size_t)s * HD) + lane);
    float4 wv = __ldg((const float4*)ew + lane);
    float4 bv = __ldg((const float4*)eb + lane);
    float m0 = fmaxf(xv.x + fmaf(a, wv.x, bv.x), 0.f);
    float m1 = fmaxf(xv.y + fmaf(a, wv.y, bv.y), 0.f);
    float m2 = fmaxf(xv.z + fmaf(a, wv.z, bv.z), 0.f);
    float m3 = fmaxf(xv.w + fmaf(a, wv.w, bv.w), 0.f);
    float* p = h + (size_t)d * HD + lane * 4;
    asm volatile("red.global.add.v4.f32 [%0], {%1, %2, %3, %4};"
                 :: "l"(p), "f"(m0), "f"(m1), "f"(m2), "f"(m3) : "memory");
}

// ---------------------------------------------------------------------------
// Fused MLP + LayerNorm + ReLU for a 64-node tile, FFMA2-packed over row pairs.
// 256 threads: ty = warp (0..7) owns rows [ty*8, ty*8+8), tx = lane owns 4 cols.
// Smem tiles stored TRANSPOSED [k][row] so a row-pair loads as one LDS.64 broadcast.
template <int DIN, bool DUAL>
__global__ void __launch_bounds__(256) mlp_ln(
        const float* __restrict__ hin,
        const float* __restrict__ w1, const float* __restrict__ b1,
        const float* __restrict__ w2, const float* __restrict__ b2,
        const float* __restrict__ gam, const float* __restrict__ bet,
        float* __restrict__ out, float* __restrict__ hdup) {
    extern __shared__ float smem[];
    float* s_inT  = smem;             // [DIN][LDT]
    float* s_midT = smem + DIN * LDT; // [HD][LDT]

    const int tid = threadIdx.x;
    const int tx = tid & 31, ty = tid >> 5;
    const int n0 = blockIdx.x * 64;
    const int cb = tx * 4;
    const int r0 = ty * 8;

    // --- fill transposed input tile ---
    if (DIN == HD) {
        for (int idx = tid; idx < 64 * 32; idx += 256) {
            int q = idx & 31, row = idx >> 5;      // coalesced float4 reads
            float4 v = __ldg((const float4*)(hin + (size_t)(n0 + row) * HD) + q);
            s_inT[(4 * q + 0) * LDT + row] = v.x;
            s_inT[(4 * q + 1) * LDT + row] = v.y;
            s_inT[(4 * q + 2) * LDT + row] = v.z;
            s_inT[(4 * q + 3) * LDT + row] = v.w;
        }
    } else {
        for (int idx = tid; idx < 64 * DIN; idx += 256) {
            int k = idx >> 6, row = idx & 63;
            s_inT[k * LDT + row] = __ldg(hin + (size_t)(n0 + row) * DIN + k);
        }
    }
    __syncthreads();

    // --- GEMM1: [64,DIN] @ [DIN,128], packed over row pairs ---
    float2 acc[4][4];
#pragma unroll
    for (int p = 0; p < 4; p++)
#pragma unroll
        for (int c = 0; c < 4; c++) acc[p][c] = make_float2(0.f, 0.f);

#pragma unroll 4
    for (int k = 0; k < DIN; k++) {
        float4 w = __ldg((const float4*)(w1 + (size_t)k * HD) + tx);
        float2 w0 = make_float2(w.x, w.x);
        float2 w1d = make_float2(w.y, w.y);
        float2 w2d = make_float2(w.z, w.z);
        float2 w3d = make_float2(w.w, w.w);
        const float2* arow = (const float2*)(s_inT + k * LDT + r0);
#pragma unroll
        for (int p = 0; p < 4; p++) {
            float2 a2 = arow[p];
            ffma2(acc[p][0], a2, w0);
            ffma2(acc[p][1], a2, w1d);
            ffma2(acc[p][2], a2, w2d);
            ffma2(acc[p][3], a2, w3d);
        }
    }

    // --- bias1 + ReLU, store mid transposed (warp-private rows) ---
    {
        float4 bb = __ldg((const float4*)b1 + tx);
#pragma unroll
        for (int c = 0; c < 4; c++) {
            float bc = (c == 0) ? bb.x : (c == 1) ? bb.y : (c == 2) ? bb.z : bb.w;
#pragma unroll
            for (int p = 0; p < 4; p++) {
                float2 m;
                m.x = fmaxf(acc[p][c].x + bc, 0.f);
                m.y = fmaxf(acc[p][c].y + bc, 0.f);
                *(float2*)(s_midT + (size_t)(cb + c) * LDT + r0 + 2 * p) = m;
            }
        }
    }
    __syncwarp();   // mid rows are warp-private: warp sync suffices

    // --- GEMM2: [64,128] @ [128,128], packed over row pairs ---
#pragma unroll
    for (int p = 0; p < 4; p++)
#pragma unroll
        for (int c = 0; c < 4; c++) acc[p][c] = make_float2(0.f, 0.f);

#pragma unroll 4
    for (int k = 0; k < HD; k++) {
        float4 w = __ldg((const float4*)(w2 + (size_t)k * HD) + tx);
        float2 w0 = make_float2(w.x, w.x);
        float2 w1d = make_float2(w.y, w.y);
        float2 w2d = make_float2(w.z, w.z);
        float2 w3d = make_float2(w.w, w.w);
        const float2* arow = (const float2*)(s_midT + k * LDT + r0);
#pragma unroll
        for (int p = 0; p < 4; p++) {
            float2 a2 = arow[p];
            ffma2(acc[p][0], a2, w0);
            ffma2(acc[p][1], a2, w1d);
            ffma2(acc[p][2], a2, w2d);
            ffma2(acc[p][3], a2, w3d);
        }
    }

    // --- bias2 + LayerNorm + ReLU + store (dual) ---
    float4 b2v = __ldg((const float4*)b2 + tx);
    float4 gv  = __ldg((const float4*)gam + tx);
    float4 bv  = __ldg((const float4*)bet + tx);
#pragma unroll
    for (int p = 0; p < 4; p++) {
#pragma unroll
        for (int rr = 0; rr < 2; rr++) {
            float v0 = (rr ? acc[p][0].y : acc[p][0].x) + b2v.x;
            float v1 = (rr ? acc[p][1].y : acc[p][1].x) + b2v.y;
            float v2 = (rr ? acc[p][2].y : acc[p][2].x) + b2v.z;
            float v3 = (rr ? acc[p][3].y : acc[p][3].x) + b2v.w;
            float s  = v0 + v1 + v2 + v3;
            float s2 = v0 * v0 + v1 * v1 + v2 * v2 + v3 * v3;
#pragma unroll
            for (int o = 16; o > 0; o >>= 1) {
                s  += __shfl_xor_sync(0xffffffffu, s, o);
                s2 += __shfl_xor_sync(0xffffffffu, s2, o);
            }
            float mean = s * (1.f / HD);
            float var  = s2 * (1.f / HD) - mean * mean;
            float rstd = rsqrtf(var + 1e-5f);
            float4 o4;
            o4.x = fmaxf((v0 - mean) * rstd * gv.x + bv.x, 0.f);
            o4.y = fmaxf((v1 - mean) * rstd * gv.y + bv.y, 0.f);
            o4.z = fmaxf((v2 - mean) * rstd * gv.z + bv.z, 0.f);
            o4.w = fmaxf((v3 - mean) * rstd * gv.w + bv.w, 0.f);
            size_t off = (size_t)(n0 + r0 + 2 * p + rr) * HD + cb;
            *(float4*)(out + off) = o4;
            if (DUAL) *(float4*)(hdup + off) = o4;
        }
    }
}

// ---------------------------------------------------------------------------
__global__ void zero_pool() {
    int i = blockIdx.x * blockDim.x + threadIdx.x;
    if (i < NG * HD) g_pool[i] = 0.f;
    if (i < NG) g_cnt[i] = 0;
}

// batch is sorted: per-block segmented running sum, atomics only at boundaries.
__global__ void pool128(const float* __restrict__ x, const int* __restrict__ batch) {
    const int CHUNK = 200;                  // 1000 blocks * 200 = 200000
    int n0 = blockIdx.x * CHUNK;
    int n1 = n0 + CHUNK;
    if (n1 > NN) n1 = NN;
    int j = threadIdx.x;                    // 128 threads = cols
    float acc = 0.f;
    int cnt = 0;
    int cur = batch[n0];
    for (int n = n0; n < n1; n++) {
        int g = batch[n];
        if (g != cur) {
            atomicAdd(&g_pool[cur * HD + j], acc);
            if (j == 0) atomicAdd(&g_cnt[cur], cnt);
            acc = 0.f; cnt = 0; cur = g;
        }
        acc += x[(size_t)n * HD + j];
        cnt++;
    }
    atomicAdd(&g_pool[cur * HD + j], acc);
    if (j == 0) atomicAdd(&g_cnt[cur], cnt);
}

__global__ void finalize(float* __restrict__ out) {
    int g = blockIdx.x, j = threadIdx.x;
    float s = g_pool[g * HD + j];
    int c = g_cnt[g];
    float cf = (float)(c > 1 ? c : 1);
    out[g * 2 * HD + j]      = s / cf;
    out[g * 2 * HD + HD + j] = s;
}

// ---------------------------------------------------------------------------
extern "C" void kernel_launch(void* const* d_in, const int* in_sizes, int n_in,
                              void* d_out, int out_size) {
    const float* x     = (const float*)d_in[0];
    const int*   ei    = (const int*)d_in[1];
    const float* ea    = (const float*)d_in[2];
    const int*   batch = (const int*)d_in[3];
    const float* P[24];
    for (int i = 0; i < 24; i++) P[i] = (const float*)d_in[4 + i];
    const int* esrc = ei;
    const int* edst = ei + NE;

    float *h5, *h, *bufA, *bufB;
    cudaGetSymbolAddress((void**)&h5, g_h5);
    cudaGetSymbolAddress((void**)&h, g_h);
    cudaGetSymbolAddress((void**)&bufA, g_bufA);
    cudaGetSymbolAddress((void**)&bufB, g_bufB);

    const int TB = 256;
    const int SM5   = (IND + HD) * LDT * (int)sizeof(float);  // 35112
    const int SM128 = (HD + HD) * LDT * (int)sizeof(float);   // 67584

    cudaFuncSetAttribute(mlp_ln<HD, true>,  cudaFuncAttributeMaxDynamicSharedMemorySize, SM128);
    cudaFuncSetAttribute(mlp_ln<HD, false>, cudaFuncAttributeMaxDynamicSharedMemorySize, SM128);

    // ---- layer 0 (din = 5) ----
    copy_f<<<(NN * IND + TB - 1) / TB, TB>>>(h5, x, NN * IND);
    edge5<<<(NE + TB - 1) / TB, TB>>>(esrc, edst, ea, P[0], P[1], x, h5);
    mlp_ln<IND, true><<<NN / 64, 256, SM5>>>(h5, P[2], P[3], P[4], P[5], P[6], P[7], bufA, h);

    // ---- layer 1 (din = 128) ----
    edge128<<<(NE * 32 + TB - 1) / TB, TB>>>(esrc, edst, ea, P[8], P[9], bufA, h);
    mlp_ln<HD, true><<<NN / 64, 256, SM128>>>(h, P[10], P[11], P[12], P[13], P[14], P[15], bufB, h);

    // ---- layer 2 (din = 128) ----
    edge128<<<(NE * 32 + TB - 1) / TB, TB>>>(esrc, edst, ea, P[16], P[17], bufB, h);
    mlp_ln<HD, false><<<NN / 64, 256, SM128>>>(h, P[18], P[19], P[20], P[21], P[22], P[23], bufA, nullptr);

    // ---- pooling ----
    zero_pool<<<(NG * HD + TB - 1) / TB, TB>>>();
    pool128<<<NN / 200, HD>>>(bufA, batch);
    finalize<<<NG, HD>>>((float*)d_out);
}

// round 4
// speedup vs baseline: 1.7501x; 1.2354x over previous
#include <cuda_runtime.h>

#define NN 200000
#define NE 400000
#define NG 64
#define HD 128
#define IND 5
#define LDA 132   // smem tile row stride (floats): conflict-free for mma frag loads

// ---------------- device scratch (allocation-free rule) ----------------
__device__ float g_h5[NN * IND];
__device__ float g_h[(size_t)NN * HD];
__device__ float g_bufA[(size_t)NN * HD];
__device__ float g_bufB[(size_t)NN * HD];
__device__ float g_pool[NG * HD];
__device__ int   g_cnt[NG];

// ---------------- helpers ----------------
__device__ __forceinline__ unsigned int f2tf32(float f) {
    unsigned int r; asm("cvt.rna.tf32.f32 %0, %1;" : "=r"(r) : "f"(f)); return r;
}
// D(16x8) += A(16x8, tf32) * B(8x8, tf32)   [m16n8k8, row.col]
__device__ __forceinline__ void mma8(float* d,
        unsigned int a0, unsigned int a1, unsigned int a2, unsigned int a3,
        unsigned int b0, unsigned int b1) {
    asm volatile("mma.sync.aligned.m16n8k8.row.col.f32.tf32.tf32.f32 "
                 "{%0,%1,%2,%3}, {%4,%5,%6,%7}, {%8,%9}, {%0,%1,%2,%3};"
                 : "+f"(d[0]), "+f"(d[1]), "+f"(d[2]), "+f"(d[3])
                 : "r"(a0), "r"(a1), "r"(a2), "r"(a3), "r"(b0), "r"(b1));
}

// ---------------- misc small kernels ----------------
__global__ void copy_f(float* __restrict__ dst, const float* __restrict__ src, int n) {
    int i = blockIdx.x * blockDim.x + threadIdx.x;
    if (i < n) dst[i] = src[i];
}

__global__ void edge5(const int* __restrict__ src, const int* __restrict__ dst,
                      const float* __restrict__ ea,
                      const float* __restrict__ ew, const float* __restrict__ eb,
                      const float* __restrict__ x, float* __restrict__ h) {
    int e = blockIdx.x * blockDim.x + threadIdx.x;
    if (e >= NE) return;
    int s = __ldg(src + e), d = __ldg(dst + e);
    float a = __ldg(ea + e);
#pragma unroll
    for (int j = 0; j < IND; j++) {
        float m = fmaxf(__ldg(x + s * IND + j) + fmaf(a, __ldg(ew + j), __ldg(eb + j)), 0.f);
        atomicAdd(&h[d * IND + j], m);
    }
}

__global__ void edge128(const int* __restrict__ src, const int* __restrict__ dst,
                        const float* __restrict__ ea,
                        const float* __restrict__ ew, const float* __restrict__ eb,
                        const float* __restrict__ x, float* __restrict__ h) {
    int t = blockIdx.x * blockDim.x + threadIdx.x;
    int e = t >> 5;
    if (e >= NE) return;
    int lane = t & 31;
    int s = __ldg(src + e), d = __ldg(dst + e);
    float a = __ldg(ea + e);
    float4 xv = __ldg((const float4*)(x + (size_t)s * HD) + lane);
    float4 wv = __ldg((const float4*)ew + lane);
    float4 bv = __ldg((const float4*)eb + lane);
    float m0 = fmaxf(xv.x + fmaf(a, wv.x, bv.x), 0.f);
    float m1 = fmaxf(xv.y + fmaf(a, wv.y, bv.y), 0.f);
    float m2 = fmaxf(xv.z + fmaf(a, wv.z, bv.z), 0.f);
    float m3 = fmaxf(xv.w + fmaf(a, wv.w, bv.w), 0.f);
    float* p = h + (size_t)d * HD + lane * 4;
    asm volatile("red.global.add.v4.f32 [%0], {%1, %2, %3, %4};"
                 :: "l"(p), "f"(m0), "f"(m1), "f"(m2), "f"(m3) : "memory");
}

// ---------------- fused MLP + LN via mma.sync tf32 ----------------
// 128-node tile, 256 threads (8 warps). Warp w owns output cols [16w, 16w+16).
// smem: biases/LN params (3KB) + A tile (128xLDA u32) + mid tile (128xLDA u32).
#define SMEM_TOT (6 * 128 * 4 + 2 * 128 * LDA * 4)

template <int DIN, bool DUAL>
__global__ void __launch_bounds__(256, 1) mlp_tc(
        const float* __restrict__ hin,
        const float* __restrict__ w1, const float* __restrict__ b1,
        const float* __restrict__ w2, const float* __restrict__ b2,
        const float* __restrict__ gam, const float* __restrict__ bet,
        float* __restrict__ out, float* __restrict__ hdup) {
    extern __shared__ char smem[];
    float* s_b1 = (float*)smem;
    float* s_b2 = s_b1 + 128;
    float* s_g  = s_b1 + 256;
    float* s_bt = s_b1 + 384;
    float* s_mu = s_b1 + 512;
    float* s_rs = s_b1 + 640;
    unsigned int* sA   = (unsigned int*)(smem + 6 * 128 * 4);
    unsigned int* sMid = sA + 128 * LDA;
    float* sAf = (float*)sA;   // reused as fp32 output staging in epilogue 2

    const int tid = threadIdx.x;
    const int w = tid >> 5, lane = tid & 31;
    const int n0 = blockIdx.x * 128;
    const int wbase = w * 16;
    const int qr = lane >> 2, qc = lane & 3;   // mma thread map

    if (tid < 128) {
        s_b1[tid] = __ldg(b1 + tid);
        s_b2[tid] = __ldg(b2 + tid);
        s_g[tid]  = __ldg(gam + tid);
        s_bt[tid] = __ldg(bet + tid);
    }

    // ---- load A tile (tf32) ----
    if (DIN == HD) {
        for (int idx = tid; idx < 128 * 32; idx += 256) {
            int row = idx >> 5, q = idx & 31;
            float4 v = make_float4(0.f, 0.f, 0.f, 0.f);
            if (n0 + row < NN) v = __ldg((const float4*)(hin + (size_t)(n0 + row) * HD) + q);
            unsigned int* p = sA + row * LDA + q * 4;
            p[0] = f2tf32(v.x); p[1] = f2tf32(v.y); p[2] = f2tf32(v.z); p[3] = f2tf32(v.w);
        }
    } else {
        for (int idx = tid; idx < 128 * 8; idx += 256) {
            int row = idx >> 3, k = idx & 7;
            float f = (n0 + row < NN && k < IND) ? __ldg(hin + (size_t)(n0 + row) * IND + k) : 0.f;
            sA[row * LDA + k] = f2tf32(f);
        }
    }

    constexpr int NK1 = (DIN == HD) ? 16 : 1;
    // ---- W1 fragments (held in regs; shared across all 8 m-tiles) ----
    unsigned int bf[2][16][2];
#pragma unroll
    for (int nt = 0; nt < 2; nt++)
#pragma unroll
        for (int k = 0; k < NK1; k++) {
            int nn = wbase + nt * 8 + qr;
            int ka = k * 8 + qc, kb = ka + 4;
            bf[nt][k][0] = (ka < DIN) ? f2tf32(__ldg(w1 + (size_t)ka * HD + nn)) : 0u;
            bf[nt][k][1] = (kb < DIN) ? f2tf32(__ldg(w1 + (size_t)kb * HD + nn)) : 0u;
        }
    __syncthreads();

    // ---- GEMM1 + bias1 + ReLU -> mid (tf32) ----
#pragma unroll 1
    for (int mt = 0; mt < 8; mt++) {
        float d0[4] = {0, 0, 0, 0}, d1[4] = {0, 0, 0, 0};
        int r0 = mt * 16 + qr;
        const unsigned int* pa = sA + r0 * LDA + qc;
        const unsigned int* pb = sA + (r0 + 8) * LDA + qc;
#pragma unroll
        for (int k = 0; k < NK1; k++) {
            unsigned int a0 = pa[k * 8], a2 = pa[k * 8 + 4];
            unsigned int a1 = pb[k * 8], a3 = pb[k * 8 + 4];
            mma8(d0, a0, a1, a2, a3, bf[0][k][0], bf[0][k][1]);
            mma8(d1, a0, a1, a2, a3, bf[1][k][0], bf[1][k][1]);
        }
#pragma unroll
        for (int nt = 0; nt < 2; nt++) {
            float* d = nt ? d1 : d0;
            int c0 = wbase + nt * 8 + qc * 2;
            unsigned int m0 = f2tf32(fmaxf(d[0] + s_b1[c0], 0.f));
            unsigned int m1 = f2tf32(fmaxf(d[1] + s_b1[c0 + 1], 0.f));
            unsigned int m2 = f2tf32(fmaxf(d[2] + s_b1[c0], 0.f));
            unsigned int m3 = f2tf32(fmaxf(d[3] + s_b1[c0 + 1], 0.f));
            *(uint2*)(sMid + r0 * LDA + c0) = make_uint2(m0, m1);
            *(uint2*)(sMid + (r0 + 8) * LDA + c0) = make_uint2(m2, m3);
        }
    }

    // ---- W2 fragments ----
#pragma unroll
    for (int nt = 0; nt < 2; nt++)
#pragma unroll
        for (int k = 0; k < 16; k++) {
            int nn = wbase + nt * 8 + qr;
            int ka = k * 8 + qc;
            bf[nt][k][0] = f2tf32(__ldg(w2 + (size_t)ka * HD + nn));
            bf[nt][k][1] = f2tf32(__ldg(w2 + (size_t)(ka + 4) * HD + nn));
        }
    __syncthreads();   // all warps done reading sA / writing sMid

    // ---- GEMM2 + bias2 -> sAf (fp32) ----
#pragma unroll 1
    for (int mt = 0; mt < 8; mt++) {
        float d0[4] = {0, 0, 0, 0}, d1[4] = {0, 0, 0, 0};
        int r0 = mt * 16 + qr;
        const unsigned int* pa = sMid + r0 * LDA + qc;
        const unsigned int* pb = sMid + (r0 + 8) * LDA + qc;
#pragma unroll
        for (int k = 0; k < 16; k++) {
            unsigned int a0 = pa[k * 8], a2 = pa[k * 8 + 4];
            unsigned int a1 = pb[k * 8], a3 = pb[k * 8 + 4];
            mma8(d0, a0, a1, a2, a3, bf[0][k][0], bf[0][k][1]);
            mma8(d1, a0, a1, a2, a3, bf[1][k][0], bf[1][k][1]);
        }
#pragma unroll
        for (int nt = 0; nt < 2; nt++) {
            float* d = nt ? d1 : d0;
            int c0 = wbase + nt * 8 + qc * 2;
            *(float2*)(sAf + r0 * LDA + c0) =
                make_float2(d[0] + s_b2[c0], d[1] + s_b2[c0 + 1]);
            *(float2*)(sAf + (r0 + 8) * LDA + c0) =
                make_float2(d[2] + s_b2[c0], d[3] + s_b2[c0 + 1]);
        }
    }
    __syncthreads();

    // ---- LayerNorm stats: 2 threads per row ----
    {
        int row = tid >> 1, half = tid & 1;
        const float* pr = sAf + row * LDA + half * 64;
        float s = 0.f, s2 = 0.f;
#pragma unroll
        for (int i = 0; i < 16; i++) {
            float4 v = *(const float4*)(pr + i * 4);
            s += v.x + v.y + v.z + v.w;
            s2 += v.x * v.x + v.y * v.y + v.z * v.z + v.w * v.w;
        }
        s  += __shfl_xor_sync(0xffffffffu, s, 1);
        s2 += __shfl_xor_sync(0xffffffffu, s2, 1);
        if (half == 0) {
            float mean = s * (1.f / HD);
            float var = s2 * (1.f / HD) - mean * mean;
            s_mu[row] = mean;
            s_rs[row] = rsqrtf(var + 1e-5f);
        }
    }
    __syncthreads();

    // ---- apply LN + ReLU, store (dual) ----
    for (int idx = tid; idx < 128 * 32; idx += 256) {
        int row = idx >> 5, q = idx & 31;
        if (n0 + row >= NN) continue;
        float mean = s_mu[row], rstd = s_rs[row];
        float4 v = *(const float4*)(sAf + row * LDA + q * 4);
        float4 o;
        o.x = fmaxf((v.x - mean) * rstd * s_g[4 * q + 0] + s_bt[4 * q + 0], 0.f);
        o.y = fmaxf((v.y - mean) * rstd * s_g[4 * q + 1] + s_bt[4 * q + 1], 0.f);
        o.z = fmaxf((v.z - mean) * rstd * s_g[4 * q + 2] + s_bt[4 * q + 2], 0.f);
        o.w = fmaxf((v.w - mean) * rstd * s_g[4 * q + 3] + s_bt[4 * q + 3], 0.f);
        size_t off = (size_t)(n0 + row) * HD + 4 * q;
        *(float4*)(out + off) = o;
        if (DUAL) *(float4*)(hdup + off) = o;
    }
}

// ---------------- pooling ----------------
__global__ void zero_pool() {
    int i = blockIdx.x * blockDim.x + threadIdx.x;
    if (i < NG * HD) g_pool[i] = 0.f;
    if (i < NG) g_cnt[i] = 0;
}

__global__ void pool128(const float* __restrict__ x, const int* __restrict__ batch) {
    const int CHUNK = 200;
    int n0 = blockIdx.x * CHUNK;
    int n1 = n0 + CHUNK;
    if (n1 > NN) n1 = NN;
    int j = threadIdx.x;
    float acc = 0.f;
    int cnt = 0;
    int cur = batch[n0];
    for (int n = n0; n < n1; n++) {
        int g = batch[n];
        if (g != cur) {
            atomicAdd(&g_pool[cur * HD + j], acc);
            if (j == 0) atomicAdd(&g_cnt[cur], cnt);
            acc = 0.f; cnt = 0; cur = g;
        }
        acc += x[(size_t)n * HD + j];
        cnt++;
    }
    atomicAdd(&g_pool[cur * HD + j], acc);
    if (j == 0) atomicAdd(&g_cnt[cur], cnt);
}

__global__ void finalize(float* __restrict__ out) {
    int g = blockIdx.x, j = threadIdx.x;
    float s = g_pool[g * HD + j];
    int c = g_cnt[g];
    float cf = (float)(c > 1 ? c : 1);
    out[g * 2 * HD + j]      = s / cf;
    out[g * 2 * HD + HD + j] = s;
}

// ---------------------------------------------------------------------------
extern "C" void kernel_launch(void* const* d_in, const int* in_sizes, int n_in,
                              void* d_out, int out_size) {
    const float* x     = (const float*)d_in[0];
    const int*   ei    = (const int*)d_in[1];
    const float* ea    = (const float*)d_in[2];
    const int*   batch = (const int*)d_in[3];
    const float* P[24];
    for (int i = 0; i < 24; i++) P[i] = (const float*)d_in[4 + i];
    const int* esrc = ei;
    const int* edst = ei + NE;

    float *h5, *h, *bufA, *bufB;
    cudaGetSymbolAddress((void**)&h5, g_h5);
    cudaGetSymbolAddress((void**)&h, g_h);
    cudaGetSymbolAddress((void**)&bufA, g_bufA);
    cudaGetSymbolAddress((void**)&bufB, g_bufB);

    cudaFuncSetAttribute(mlp_tc<IND, true>, cudaFuncAttributeMaxDynamicSharedMemorySize, SMEM_TOT);
    cudaFuncSetAttribute(mlp_tc<HD, true>,  cudaFuncAttributeMaxDynamicSharedMemorySize, SMEM_TOT);
    cudaFuncSetAttribute(mlp_tc<HD, false>, cudaFuncAttributeMaxDynamicSharedMemorySize, SMEM_TOT);

    const int TB = 256;
    const int GMLP = (NN + 127) / 128;

    // ---- layer 0 (din = 5) ----
    copy_f<<<(NN * IND + TB - 1) / TB, TB>>>(h5, x, NN * IND);
    edge5<<<(NE + TB - 1) / TB, TB>>>(esrc, edst, ea, P[0], P[1], x, h5);
    mlp_tc<IND, true><<<GMLP, 256, SMEM_TOT>>>(h5, P[2], P[3], P[4], P[5], P[6], P[7], bufA, h);

    // ---- layer 1 ----
    edge128<<<(NE * 32 + TB - 1) / TB, TB>>>(esrc, edst, ea, P[8], P[9], bufA, h);
    mlp_tc<HD, true><<<GMLP, 256, SMEM_TOT>>>(h, P[10], P[11], P[12], P[13], P[14], P[15], bufB, h);

    // ---- layer 2 ----
    edge128<<<(NE * 32 + TB - 1) / TB, TB>>>(esrc, edst, ea, P[16], P[17], bufB, h);
    mlp_tc<HD, false><<<GMLP, 256, SMEM_TOT>>>(h, P[18], P[19], P[20], P[21], P[22], P[23], bufA, nullptr);

    // ---- pooling ----
    zero_pool<<<(NG * HD + TB - 1) / TB, TB>>>();
    pool128<<<NN / 200, HD>>>(bufA, batch);
    finalize<<<NG, HD>>>((float*)d_out);
}

// round 5
// speedup vs baseline: 2.1646x; 1.2369x over previous
#include <cuda_runtime.h>

#define NN 200000
#define NE 400000
#define NG 64
#define HD 128
#define IND 5
#define LDA 132   // smem tile row stride (floats): conflict-free for mma frag loads
#define TROWS 64  // node rows per block tile

// ---------------- device scratch (allocation-free rule) ----------------
__device__ float g_h5[NN * IND];
__device__ float g_h[(size_t)NN * HD];
__device__ float g_bufA[(size_t)NN * HD];
__device__ float g_bufB[(size_t)NN * HD];
__device__ float g_pool[NG * HD];
__device__ int   g_cnt[NG];

// ---------------- helpers ----------------
__device__ __forceinline__ unsigned int f2tf32(float f) {
    unsigned int r; asm("cvt.rna.tf32.f32 %0, %1;" : "=r"(r) : "f"(f)); return r;
}
// D(16x8) += A(16x8, tf32) * B(8x8, tf32)   [m16n8k8, row.col]
__device__ __forceinline__ void mma8(float* d,
        unsigned int a0, unsigned int a1, unsigned int a2, unsigned int a3,
        unsigned int b0, unsigned int b1) {
    asm volatile("mma.sync.aligned.m16n8k8.row.col.f32.tf32.tf32.f32 "
                 "{%0,%1,%2,%3}, {%4,%5,%6,%7}, {%8,%9}, {%0,%1,%2,%3};"
                 : "+f"(d[0]), "+f"(d[1]), "+f"(d[2]), "+f"(d[3])
                 : "r"(a0), "r"(a1), "r"(a2), "r"(a3), "r"(b0), "r"(b1));
}

// ---------------- misc small kernels ----------------
__global__ void copy_f(float* __restrict__ dst, const float* __restrict__ src, int n) {
    int i = blockIdx.x * blockDim.x + threadIdx.x;
    if (i < n) dst[i] = src[i];
}

__global__ void edge5(const int* __restrict__ src, const int* __restrict__ dst,
                      const float* __restrict__ ea,
                      const float* __restrict__ ew, const float* __restrict__ eb,
                      const float* __restrict__ x, float* __restrict__ h) {
    int e = blockIdx.x * blockDim.x + threadIdx.x;
    if (e >= NE) return;
    int s = __ldg(src + e), d = __ldg(dst + e);
    float a = __ldg(ea + e);
#pragma unroll
    for (int j = 0; j < IND; j++) {
        float m = fmaxf(__ldg(x + s * IND + j) + fmaf(a, __ldg(ew + j), __ldg(eb + j)), 0.f);
        atomicAdd(&h[d * IND + j], m);
    }
}

__global__ void edge128(const int* __restrict__ src, const int* __restrict__ dst,
                        const float* __restrict__ ea,
                        const float* __restrict__ ew, const float* __restrict__ eb,
                        const float* __restrict__ x, float* __restrict__ h) {
    int t = blockIdx.x * blockDim.x + threadIdx.x;
    int e = t >> 5;
    if (e >= NE) return;
    int lane = t & 31;
    int s = __ldg(src + e), d = __ldg(dst + e);
    float a = __ldg(ea + e);
    float4 xv = __ldg((const float4*)(x + (size_t)s * HD) + lane);
    float4 wv = __ldg((const float4*)ew + lane);
    float4 bv = __ldg((const float4*)eb + lane);
    float m0 = fmaxf(xv.x + fmaf(a, wv.x, bv.x), 0.f);
    float m1 = fmaxf(xv.y + fmaf(a, wv.y, bv.y), 0.f);
    float m2 = fmaxf(xv.z + fmaf(a, wv.z, bv.z), 0.f);
    float m3 = fmaxf(xv.w + fmaf(a, wv.w, bv.w), 0.f);
    float* p = h + (size_t)d * HD + lane * 4;
    asm volatile("red.global.add.v4.f32 [%0], {%1, %2, %3, %4};"
                 :: "l"(p), "f"(m0), "f"(m1), "f"(m2), "f"(m3) : "memory");
}

// ---------------- fused MLP + LN via mma.sync tf32 ----------------
// 64-node tile, 256 threads (8 warps). Warp w owns output cols [16w, 16w+16).
// smem: params (3KB) + A tile (64xLDA u32) + mid tile (64xLDA u32) = ~70.6KB -> 2 CTAs/SM.
#define SMEM_TOT (6 * 128 * 4 + 2 * TROWS * LDA * 4)

template <int DIN, bool DUAL>
__global__ void __launch_bounds__(256, 2) mlp_tc(
        const float* __restrict__ hin,
        const float* __restrict__ w1, const float* __restrict__ b1,
        const float* __restrict__ w2, const float* __restrict__ b2,
        const float* __restrict__ gam, const float* __restrict__ bet,
        float* __restrict__ out, float* __restrict__ hdup) {
    extern __shared__ char smem[];
    float* s_b1 = (float*)smem;
    float* s_b2 = s_b1 + 128;
    float* s_g  = s_b1 + 256;
    float* s_bt = s_b1 + 384;
    float* s_mu = s_b1 + 512;
    float* s_rs = s_b1 + 640;
    unsigned int* sA   = (unsigned int*)(smem + 6 * 128 * 4);
    unsigned int* sMid = sA + TROWS * LDA;
    float* sAf = (float*)sA;   // reused as fp32 output staging in epilogue 2

    const int tid = threadIdx.x;
    const int w = tid >> 5, lane = tid & 31;
    const int n0 = blockIdx.x * TROWS;
    const int wbase = w * 16;
    const int qr = lane >> 2, qc = lane & 3;   // mma thread map

    if (tid < 128) {
        s_b1[tid] = __ldg(b1 + tid);
        s_b2[tid] = __ldg(b2 + tid);
        s_g[tid]  = __ldg(gam + tid);
        s_bt[tid] = __ldg(bet + tid);
    }

    // ---- load A tile (tf32) ----
    if (DIN == HD) {
        for (int idx = tid; idx < TROWS * 32; idx += 256) {
            int row = idx >> 5, q = idx & 31;
            float4 v = __ldg((const float4*)(hin + (size_t)(n0 + row) * HD) + q);
            unsigned int* p = sA + row * LDA + q * 4;
            p[0] = f2tf32(v.x); p[1] = f2tf32(v.y); p[2] = f2tf32(v.z); p[3] = f2tf32(v.w);
        }
    } else {
        for (int idx = tid; idx < TROWS * 8; idx += 256) {
            int row = idx >> 3, k = idx & 7;
            float f = (k < IND) ? __ldg(hin + (size_t)(n0 + row) * IND + k) : 0.f;
            sA[row * LDA + k] = f2tf32(f);
        }
    }

    constexpr int NK1 = (DIN == HD) ? 16 : 1;
    // ---- W1 fragments (held in regs; shared across all m-tiles) ----
    unsigned int bf[2][16][2];
#pragma unroll
    for (int nt = 0; nt < 2; nt++)
#pragma unroll
        for (int k = 0; k < NK1; k++) {
            int nn = wbase + nt * 8 + qr;
            int ka = k * 8 + qc, kb = ka + 4;
            bf[nt][k][0] = (ka < DIN) ? f2tf32(__ldg(w1 + (size_t)ka * HD + nn)) : 0u;
            bf[nt][k][1] = (kb < DIN) ? f2tf32(__ldg(w1 + (size_t)kb * HD + nn)) : 0u;
        }
    __syncthreads();

    // ---- GEMM1 + bias1 + ReLU -> mid (tf32) ----
#pragma unroll 1
    for (int mt = 0; mt < TROWS / 16; mt++) {
        float d0[4] = {0, 0, 0, 0}, d1[4] = {0, 0, 0, 0};
        int r0 = mt * 16 + qr;
        const unsigned int* pa = sA + r0 * LDA + qc;
        const unsigned int* pb = sA + (r0 + 8) * LDA + qc;
#pragma unroll
        for (int k = 0; k < NK1; k++) {
            unsigned int a0 = pa[k * 8], a2 = pa[k * 8 + 4];
            unsigned int a1 = pb[k * 8], a3 = pb[k * 8 + 4];
            mma8(d0, a0, a1, a2, a3, bf[0][k][0], bf[0][k][1]);
            mma8(d1, a0, a1, a2, a3, bf[1][k][0], bf[1][k][1]);
        }
#pragma unroll
        for (int nt = 0; nt < 2; nt++) {
            float* d = nt ? d1 : d0;
            int c0 = wbase + nt * 8 + qc * 2;
            unsigned int m0 = f2tf32(fmaxf(d[0] + s_b1[c0], 0.f));
            unsigned int m1 = f2tf32(fmaxf(d[1] + s_b1[c0 + 1], 0.f));
            unsigned int m2 = f2tf32(fmaxf(d[2] + s_b1[c0], 0.f));
            unsigned int m3 = f2tf32(fmaxf(d[3] + s_b1[c0 + 1], 0.f));
            *(uint2*)(sMid + r0 * LDA + c0) = make_uint2(m0, m1);
            *(uint2*)(sMid + (r0 + 8) * LDA + c0) = make_uint2(m2, m3);
        }
    }

    // ---- W2 fragments ----
#pragma unroll
    for (int nt = 0; nt < 2; nt++)
#pragma unroll
        for (int k = 0; k < 16; k++) {
            int nn = wbase + nt * 8 + qr;
            int ka = k * 8 + qc;
            bf[nt][k][0] = f2tf32(__ldg(w2 + (size_t)ka * HD + nn));
            bf[nt][k][1] = f2tf32(__ldg(w2 + (size_t)(ka + 4) * HD + nn));
        }
    __syncthreads();   // all warps done reading sA / writing sMid

    // ---- GEMM2 + bias2 -> sAf (fp32) ----
#pragma unroll 1
    for (int mt = 0; mt < TROWS / 16; mt++) {
        float d0[4] = {0, 0, 0, 0}, d1[4] = {0, 0, 0, 0};
        int r0 = mt * 16 + qr;
        const unsigned int* pa = sMid + r0 * LDA + qc;
        const unsigned int* pb = sMid + (r0 + 8) * LDA + qc;
#pragma unroll
        for (int k = 0; k < 16; k++) {
            unsigned int a0 = pa[k * 8], a2 = pa[k * 8 + 4];
            unsigned int a1 = pb[k * 8], a3 = pb[k * 8 + 4];
            mma8(d0, a0, a1, a2, a3, bf[0][k][0], bf[0][k][1]);
            mma8(d1, a0, a1, a2, a3, bf[1][k][0], bf[1][k][1]);
        }
#pragma unroll
        for (int nt = 0; nt < 2; nt++) {
            float* d = nt ? d1 : d0;
            int c0 = wbase + nt * 8 + qc * 2;
            *(float2*)(sAf + r0 * LDA + c0) =
                make_float2(d[0] + s_b2[c0], d[1] + s_b2[c0 + 1]);
            *(float2*)(sAf + (r0 + 8) * LDA + c0) =
                make_float2(d[2] + s_b2[c0], d[3] + s_b2[c0 + 1]);
        }
    }
    __syncthreads();

    // ---- LayerNorm stats: 2 threads per row (rows 0..TROWS) ----
    if (tid < TROWS * 2) {
        int row = tid >> 1, half = tid & 1;
        const float* pr = sAf + row * LDA + half * 64;
        float s = 0.f, s2 = 0.f;
#pragma unroll
        for (int i = 0; i < 16; i++) {
            float4 v = *(const float4*)(pr + i * 4);
            s += v.x + v.y + v.z + v.w;
            s2 += v.x * v.x + v.y * v.y + v.z * v.z + v.w * v.w;
        }
        s  += __shfl_xor_sync(0xffffffffu, s, 1);
        s2 += __shfl_xor_sync(0xffffffffu, s2, 1);
        if (half == 0) {
            float mean = s * (1.f / HD);
            float var = s2 * (1.f / HD) - mean * mean;
            s_mu[row] = mean;
            s_rs[row] = rsqrtf(var + 1e-5f);
        }
    }
    __syncthreads();

    // ---- apply LN + ReLU, store (dual) ----
    for (int idx = tid; idx < TROWS * 32; idx += 256) {
        int row = idx >> 5, q = idx & 31;
        float mean = s_mu[row], rstd = s_rs[row];
        float4 v = *(const float4*)(sAf + row * LDA + q * 4);
        float4 o;
        o.x = fmaxf((v.x - mean) * rstd * s_g[4 * q + 0] + s_bt[4 * q + 0], 0.f);
        o.y = fmaxf((v.y - mean) * rstd * s_g[4 * q + 1] + s_bt[4 * q + 1], 0.f);
        o.z = fmaxf((v.z - mean) * rstd * s_g[4 * q + 2] + s_bt[4 * q + 2], 0.f);
        o.w = fmaxf((v.w - mean) * rstd * s_g[4 * q + 3] + s_bt[4 * q + 3], 0.f);
        size_t off = (size_t)(n0 + row) * HD + 4 * q;
        *(float4*)(out + off) = o;
        if (DUAL) *(float4*)(hdup + off) = o;
    }
}

// ---------------- pooling ----------------
__global__ void zero_pool() {
    int i = blockIdx.x * blockDim.x + threadIdx.x;
    if (i < NG * HD) g_pool[i] = 0.f;
    if (i < NG) g_cnt[i] = 0;
}

__global__ void pool128(const float* __restrict__ x, const int* __restrict__ batch) {
    const int CHUNK = 200;
    int n0 = blockIdx.x * CHUNK;
    int n1 = n0 + CHUNK;
    if (n1 > NN) n1 = NN;
    int j = threadIdx.x;
    float acc = 0.f;
    int cnt = 0;
    int cur = batch[n0];
    for (int n = n0; n < n1; n++) {
        int g = batch[n];
        if (g != cur) {
            atomicAdd(&g_pool[cur * HD + j], acc);
            if (j == 0) atomicAdd(&g_cnt[cur], cnt);
            acc = 0.f; cnt = 0; cur = g;
        }
        acc += x[(size_t)n * HD + j];
        cnt++;
    }
    atomicAdd(&g_pool[cur * HD + j], acc);
    if (j == 0) atomicAdd(&g_cnt[cur], cnt);
}

__global__ void finalize(float* __restrict__ out) {
    int g = blockIdx.x, j = threadIdx.x;
    float s = g_pool[g * HD + j];
    int c = g_cnt[g];
    float cf = (float)(c > 1 ? c : 1);
    out[g * 2 * HD + j]      = s / cf;
    out[g * 2 * HD + HD + j] = s;
}

// ---------------------------------------------------------------------------
extern "C" void kernel_launch(void* const* d_in, const int* in_sizes, int n_in,
                              void* d_out, int out_size) {
    const float* x     = (const float*)d_in[0];
    const int*   ei    = (const int*)d_in[1];
    const float* ea    = (const float*)d_in[2];
    const int*   batch = (const int*)d_in[3];
    const float* P[24];
    for (int i = 0; i < 24; i++) P[i] = (const float*)d_in[4 + i];
    const int* esrc = ei;
    const int* edst = ei + NE;

    float *h5, *h, *bufA, *bufB;
    cudaGetSymbolAddress((void**)&h5, g_h5);
    cudaGetSymbolAddress((void**)&h, g_h);
    cudaGetSymbolAddress((void**)&bufA, g_bufA);
    cudaGetSymbolAddress((void**)&bufB, g_bufB);

    cudaFuncSetAttribute(mlp_tc<IND, true>, cudaFuncAttributeMaxDynamicSharedMemorySize, SMEM_TOT);
    cudaFuncSetAttribute(mlp_tc<HD, true>,  cudaFuncAttributeMaxDynamicSharedMemorySize, SMEM_TOT);
    cudaFuncSetAttribute(mlp_tc<HD, false>, cudaFuncAttributeMaxDynamicSharedMemorySize, SMEM_TOT);

    const int TB = 256;
    const int GMLP = NN / TROWS;   // 200000 / 64 = 3125

    // ---- layer 0 (din = 5) ----
    copy_f<<<(NN * IND + TB - 1) / TB, TB>>>(h5, x, NN * IND);
    edge5<<<(NE + TB - 1) / TB, TB>>>(esrc, edst, ea, P[0], P[1], x, h5);
    mlp_tc<IND, true><<<GMLP, 256, SMEM_TOT>>>(h5, P[2], P[3], P[4], P[5], P[6], P[7], bufA, h);

    // ---- layer 1 ----
    edge128<<<(NE * 32 + TB - 1) / TB, TB>>>(esrc, edst, ea, P[8], P[9], bufA, h);
    mlp_tc<HD, true><<<GMLP, 256, SMEM_TOT>>>(h, P[10], P[11], P[12], P[13], P[14], P[15], bufB, h);

    // ---- layer 2 ----
    edge128<<<(NE * 32 + TB - 1) / TB, TB>>>(esrc, edst, ea, P[16], P[17], bufB, h);
    mlp_tc<HD, false><<<GMLP, 256, SMEM_TOT>>>(h, P[18], P[19], P[20], P[21], P[22], P[23], bufA, nullptr);

    // ---- pooling ----
    zero_pool<<<(NG * HD + TB - 1) / TB, TB>>>();
    pool128<<<NN / 200, HD>>>(bufA, batch);
    finalize<<<NG, HD>>>((float*)d_out);
}

// round 6
// speedup vs baseline: 3.0098x; 1.3905x over previous
#include <cuda_runtime.h>
#include <cuda_fp16.h>

#define NN 200000
#define NE 400000
#define NG 64
#define HD 128
#define IND 5
#define TROWS 64
#define SROW 136        // f16 tile row stride (halves): ldmatrix conflict-free
#define LDAF 132        // fp32 staging row stride (floats)
#define GRID_P 304      // persistent CTAs (2 per SM)

// ---------------- device scratch (allocation-free rule) ----------------
__device__ float g_h5[NN * IND];
__device__ float g_h[(size_t)NN * HD];
__device__ float g_bufA[(size_t)NN * HD];
__device__ float g_bufB[(size_t)NN * HD];
__device__ float g_pool[NG * HD];
__device__ int   g_cnt[NG];

// ---------------- helpers ----------------
__device__ __forceinline__ unsigned packh2(float a, float b) {
    half2 h = __floats2half2_rn(a, b);
    return *(unsigned*)&h;
}
__device__ __forceinline__ void ldmA(unsigned a[4], unsigned saddr) {
    asm volatile("ldmatrix.sync.aligned.m8n8.x4.shared.b16 {%0,%1,%2,%3}, [%4];"
                 : "=r"(a[0]), "=r"(a[1]), "=r"(a[2]), "=r"(a[3]) : "r"(saddr));
}
__device__ __forceinline__ void mma16(float* d, const unsigned* a, unsigned b0, unsigned b1) {
    asm volatile("mma.sync.aligned.m16n8k16.row.col.f32.f16.f16.f32 "
                 "{%0,%1,%2,%3}, {%4,%5,%6,%7}, {%8,%9}, {%0,%1,%2,%3};"
                 : "+f"(d[0]), "+f"(d[1]), "+f"(d[2]), "+f"(d[3])
                 : "r"(a[0]), "r"(a[1]), "r"(a[2]), "r"(a[3]), "r"(b0), "r"(b1));
}

// ---------------- misc small kernels ----------------
__global__ void copy_f(float* __restrict__ dst, const float* __restrict__ src, int n) {
    int i = blockIdx.x * blockDim.x + threadIdx.x;
    if (i < n) dst[i] = src[i];
}

__global__ void edge5(const int* __restrict__ src, const int* __restrict__ dst,
                      const float* __restrict__ ea,
                      const float* __restrict__ ew, const float* __restrict__ eb,
                      const float* __restrict__ x, float* __restrict__ h) {
    int e = blockIdx.x * blockDim.x + threadIdx.x;
    if (e >= NE) return;
    int s = __ldg(src + e), d = __ldg(dst + e);
    float a = __ldg(ea + e);
#pragma unroll
    for (int j = 0; j < IND; j++) {
        float m = fmaxf(__ldg(x + s * IND + j) + fmaf(a, __ldg(ew + j), __ldg(eb + j)), 0.f);
        atomicAdd(&h[d * IND + j], m);
    }
}

__global__ void edge128(const int* __restrict__ src, const int* __restrict__ dst,
                        const float* __restrict__ ea,
                        const float* __restrict__ ew, const float* __restrict__ eb,
                        const float* __restrict__ x, float* __restrict__ h) {
    int t = blockIdx.x * blockDim.x + threadIdx.x;
    int e = t >> 5;
    if (e >= NE) return;
    int lane = t & 31;
    int s = __ldg(src + e), d = __ldg(dst + e);
    float a = __ldg(ea + e);
    float4 xv = __ldg((const float4*)(x + (size_t)s * HD) + lane);
    float4 wv = __ldg((const float4*)ew + lane);
    float4 bv = __ldg((const float4*)eb + lane);
    float m0 = fmaxf(xv.x + fmaf(a, wv.x, bv.x), 0.f);
    float m1 = fmaxf(xv.y + fmaf(a, wv.y, bv.y), 0.f);
    float m2 = fmaxf(xv.z + fmaf(a, wv.z, bv.z), 0.f);
    float m3 = fmaxf(xv.w + fmaf(a, wv.w, bv.w), 0.f);
    float* p = h + (size_t)d * HD + lane * 4;
    asm volatile("red.global.add.v4.f32 [%0], {%1, %2, %3, %4};"
                 :: "l"(p), "f"(m0), "f"(m1), "f"(m2), "f"(m3) : "memory");
}

// ---------------- fused MLP + LN, fp16 m16n8k16, persistent ----------------
// smem layout (bytes): [0,3072) params, [3072) sA f16 64xSROW, [20480) sMid f16,
//                      [37888) sAf fp32 64xLDAF  -> total 71680 (2 CTAs/SM)
#define OFF_A   3072
#define OFF_MID 20480
#define OFF_AF  37888
#define SMEM_TOT (OFF_AF + TROWS * LDAF * 4)
#define NTILE (NN / TROWS)

template <int DIN, bool DUAL>
__global__ void __launch_bounds__(256, 2) mlp_tc(
        const float* __restrict__ hin,
        const float* __restrict__ w1, const float* __restrict__ b1,
        const float* __restrict__ w2, const float* __restrict__ b2,
        const float* __restrict__ gam, const float* __restrict__ bet,
        float* __restrict__ out, float* __restrict__ hdup) {
    extern __shared__ char smem[];
    float* s_b1 = (float*)smem;
    float* s_b2 = s_b1 + 128;
    float* s_g  = s_b1 + 256;
    float* s_bt = s_b1 + 384;
    float* s_mu = s_b1 + 512;
    float* s_rs = s_b1 + 640;
    half*  sA   = (half*)(smem + OFF_A);
    half*  sMid = (half*)(smem + OFF_MID);
    float* sAf  = (float*)(smem + OFF_AF);

    const int tid = threadIdx.x;
    const int w = tid >> 5, lane = tid & 31;
    const int qr = lane >> 2, qc = lane & 3;
    const int wbase = w * 16;
    // ldmatrix lane address components (row/col within 16x16 tile)
    const int lm_r = ((lane >> 3) & 1) * 8 + (lane & 7);
    const int lm_c = (lane >> 4) * 8;

    if (tid < 128) {
        s_b1[tid] = __ldg(b1 + tid);
        s_b2[tid] = __ldg(b2 + tid);
        s_g[tid]  = __ldg(gam + tid);
        s_bt[tid] = __ldg(bet + tid);
    }

    // ---- W fragments: loaded ONCE per persistent CTA ----
    constexpr int NKS1 = (DIN == HD) ? 8 : 1;
    unsigned wf1[2][NKS1][2], wf2[2][8][2];
#pragma unroll
    for (int nt = 0; nt < 2; nt++) {
        int n = wbase + nt * 8 + qr;
#pragma unroll
        for (int kk = 0; kk < NKS1; kk++) {
            int k0 = kk * 16 + 2 * qc;
            float f0 = (k0 < DIN)     ? __ldg(w1 + (size_t)k0 * HD + n)       : 0.f;
            float f1 = (k0 + 1 < DIN) ? __ldg(w1 + (size_t)(k0 + 1) * HD + n) : 0.f;
            float f2 = (k0 + 8 < DIN) ? __ldg(w1 + (size_t)(k0 + 8) * HD + n) : 0.f;
            float f3 = (k0 + 9 < DIN) ? __ldg(w1 + (size_t)(k0 + 9) * HD + n) : 0.f;
            wf1[nt][kk][0] = packh2(f0, f1);
            wf1[nt][kk][1] = packh2(f2, f3);
        }
#pragma unroll
        for (int kk = 0; kk < 8; kk++) {
            int k0 = kk * 16 + 2 * qc;
            wf2[nt][kk][0] = packh2(__ldg(w2 + (size_t)k0 * HD + n),
                                    __ldg(w2 + (size_t)(k0 + 1) * HD + n));
            wf2[nt][kk][1] = packh2(__ldg(w2 + (size_t)(k0 + 8) * HD + n),
                                    __ldg(w2 + (size_t)(k0 + 9) * HD + n));
        }
    }
    __syncthreads();

    const unsigned sA_base   = (unsigned)__cvta_generic_to_shared(sA);
    const unsigned sMid_base = (unsigned)__cvta_generic_to_shared(sMid);

    for (int tile = blockIdx.x; tile < NTILE; tile += GRID_P) {
        const int n0 = tile * TROWS;

        // ---- A tile -> f16 smem ----
        if (DIN == HD) {
            for (int idx = tid; idx < TROWS * 32; idx += 256) {
                int row = idx >> 5, q = idx & 31;
                float4 v = __ldg((const float4*)(hin + (size_t)(n0 + row) * HD) + q);
                *(uint2*)(sA + row * SROW + q * 4) =
                    make_uint2(packh2(v.x, v.y), packh2(v.z, v.w));
            }
        } else {
            for (int idx = tid; idx < TROWS * 16; idx += 256) {
                int row = idx >> 4, k = idx & 15;
                float f = (k < IND) ? __ldg(hin + (size_t)(n0 + row) * IND + k) : 0.f;
                sA[row * SROW + k] = __float2half_rn(f);
            }
        }
        __syncthreads();

        // ---- GEMM1 + bias1 + ReLU -> sMid (f16) ----
#pragma unroll 1
        for (int mt = 0; mt < TROWS / 16; mt++) {
            float d0[4] = {0, 0, 0, 0}, d1[4] = {0, 0, 0, 0};
            int r0 = mt * 16;
#pragma unroll
            for (int kk = 0; kk < NKS1; kk++) {
                unsigned a[4];
                ldmA(a, sA_base + ((r0 + lm_r) * SROW + kk * 16 + lm_c) * 2);
                mma16(d0, a, wf1[0][kk][0], wf1[0][kk][1]);
                mma16(d1, a, wf1[1][kk][0], wf1[1][kk][1]);
            }
#pragma unroll
            for (int nt = 0; nt < 2; nt++) {
                float* d = nt ? d1 : d0;
                int c0 = wbase + nt * 8 + 2 * qc;
                *(unsigned*)(sMid + (r0 + qr) * SROW + c0) =
                    packh2(fmaxf(d[0] + s_b1[c0], 0.f), fmaxf(d[1] + s_b1[c0 + 1], 0.f));
                *(unsigned*)(sMid + (r0 + 8 + qr) * SROW + c0) =
                    packh2(fmaxf(d[2] + s_b1[c0], 0.f), fmaxf(d[3] + s_b1[c0 + 1], 0.f));
            }
        }
        __syncthreads();

        // ---- GEMM2 + bias2 -> sAf (fp32) ----
#pragma unroll 1
        for (int mt = 0; mt < TROWS / 16; mt++) {
            float d0[4] = {0, 0, 0, 0}, d1[4] = {0, 0, 0, 0};
            int r0 = mt * 16;
#pragma unroll
            for (int kk = 0; kk < 8; kk++) {
                unsigned a[4];
                ldmA(a, sMid_base + ((r0 + lm_r) * SROW + kk * 16 + lm_c) * 2);
                mma16(d0, a, wf2[0][kk][0], wf2[0][kk][1]);
                mma16(d1, a, wf2[1][kk][0], wf2[1][kk][1]);
            }
#pragma unroll
            for (int nt = 0; nt < 2; nt++) {
                float* d = nt ? d1 : d0;
                int c0 = wbase + nt * 8 + 2 * qc;
                *(float2*)(sAf + (r0 + qr) * LDAF + c0) =
                    make_float2(d[0] + s_b2[c0], d[1] + s_b2[c0 + 1]);
                *(float2*)(sAf + (r0 + 8 + qr) * LDAF + c0) =
                    make_float2(d[2] + s_b2[c0], d[3] + s_b2[c0 + 1]);
            }
        }
        __syncthreads();

        // ---- LayerNorm stats: 2 threads per row ----
        if (tid < TROWS * 2) {
            int row = tid >> 1, half_ = tid & 1;
            const float* pr = sAf + row * LDAF + half_ * 64;
            float s = 0.f, s2 = 0.f;
#pragma unroll
            for (int i = 0; i < 16; i++) {
                float4 v = *(const float4*)(pr + i * 4);
                s += v.x + v.y + v.z + v.w;
                s2 += v.x * v.x + v.y * v.y + v.z * v.z + v.w * v.w;
            }
            s  += __shfl_xor_sync(0xffffffffu, s, 1);
            s2 += __shfl_xor_sync(0xffffffffu, s2, 1);
            if (half_ == 0) {
                float mean = s * (1.f / HD);
                float var = s2 * (1.f / HD) - mean * mean;
                s_mu[row] = mean;
                s_rs[row] = rsqrtf(var + 1e-5f);
            }
        }
        __syncthreads();

        // ---- apply LN + ReLU, store (dual) ----
        for (int idx = tid; idx < TROWS * 32; idx += 256) {
            int row = idx >> 5, q = idx & 31;
            float mean = s_mu[row], rstd = s_rs[row];
            float4 v = *(const float4*)(sAf + row * LDAF + q * 4);
            float4 o;
            o.x = fmaxf((v.x - mean) * rstd * s_g[4 * q + 0] + s_bt[4 * q + 0], 0.f);
            o.y = fmaxf((v.y - mean) * rstd * s_g[4 * q + 1] + s_bt[4 * q + 1], 0.f);
            o.z = fmaxf((v.z - mean) * rstd * s_g[4 * q + 2] + s_bt[4 * q + 2], 0.f);
            o.w = fmaxf((v.w - mean) * rstd * s_g[4 * q + 3] + s_bt[4 * q + 3], 0.f);
            size_t off = (size_t)(n0 + row) * HD + 4 * q;
            *(float4*)(out + off) = o;
            if (DUAL) *(float4*)(hdup + off) = o;
        }
        __syncthreads();
    }
}

// ---------------- pooling ----------------
__global__ void zero_pool() {
    int i = blockIdx.x * blockDim.x + threadIdx.x;
    if (i < NG * HD) g_pool[i] = 0.f;
    if (i < NG) g_cnt[i] = 0;
}

__global__ void pool128(const float* __restrict__ x, const int* __restrict__ batch) {
    const int CHUNK = 200;
    int n0 = blockIdx.x * CHUNK;
    int n1 = n0 + CHUNK;
    if (n1 > NN) n1 = NN;
    int j = threadIdx.x;
    float acc = 0.f;
    int cnt = 0;
    int cur = batch[n0];
    for (int n = n0; n < n1; n++) {
        int g = batch[n];
        if (g != cur) {
            atomicAdd(&g_pool[cur * HD + j], acc);
            if (j == 0) atomicAdd(&g_cnt[cur], cnt);
            acc = 0.f; cnt = 0; cur = g;
        }
        acc += x[(size_t)n * HD + j];
        cnt++;
    }
    atomicAdd(&g_pool[cur * HD + j], acc);
    if (j == 0) atomicAdd(&g_cnt[cur], cnt);
}

__global__ void finalize(float* __restrict__ out) {
    int g = blockIdx.x, j = threadIdx.x;
    float s = g_pool[g * HD + j];
    int c = g_cnt[g];
    float cf = (float)(c > 1 ? c : 1);
    out[g * 2 * HD + j]      = s / cf;
    out[g * 2 * HD + HD + j] = s;
}

// ---------------------------------------------------------------------------
extern "C" void kernel_launch(void* const* d_in, const int* in_sizes, int n_in,
                              void* d_out, int out_size) {
    const float* x     = (const float*)d_in[0];
    const int*   ei    = (const int*)d_in[1];
    const float* ea    = (const float*)d_in[2];
    const int*   batch = (const int*)d_in[3];
    const float* P[24];
    for (int i = 0; i < 24; i++) P[i] = (const float*)d_in[4 + i];
    const int* esrc = ei;
    const int* edst = ei + NE;

    float *h5, *h, *bufA, *bufB;
    cudaGetSymbolAddress((void**)&h5, g_h5);
    cudaGetSymbolAddress((void**)&h, g_h);
    cudaGetSymbolAddress((void**)&bufA, g_bufA);
    cudaGetSymbolAddress((void**)&bufB, g_bufB);

    cudaFuncSetAttribute(mlp_tc<IND, true>, cudaFuncAttributeMaxDynamicSharedMemorySize, SMEM_TOT);
    cudaFuncSetAttribute(mlp_tc<HD, true>,  cudaFuncAttributeMaxDynamicSharedMemorySize, SMEM_TOT);
    cudaFuncSetAttribute(mlp_tc<HD, false>, cudaFuncAttributeMaxDynamicSharedMemorySize, SMEM_TOT);

    const int TB = 256;

    // ---- layer 0 (din = 5) ----
    copy_f<<<(NN * IND + TB - 1) / TB, TB>>>(h5, x, NN * IND);
    edge5<<<(NE + TB - 1) / TB, TB>>>(esrc, edst, ea, P[0], P[1], x, h5);
    mlp_tc<IND, true><<<GRID_P, 256, SMEM_TOT>>>(h5, P[2], P[3], P[4], P[5], P[6], P[7], bufA, h);

    // ---- layer 1 ----
    edge128<<<(NE * 32 + TB - 1) / TB, TB>>>(esrc, edst, ea, P[8], P[9], bufA, h);
    mlp_tc<HD, true><<<GRID_P, 256, SMEM_TOT>>>(h, P[10], P[11], P[12], P[13], P[14], P[15], bufB, h);

    // ---- layer 2 ----
    edge128<<<(NE * 32 + TB - 1) / TB, TB>>>(esrc, edst, ea, P[16], P[17], bufB, h);
    mlp_tc<HD, false><<<GRID_P, 256, SMEM_TOT>>>(h, P[18], P[19], P[20], P[21], P[22], P[23], bufA, nullptr);

    // ---- pooling ----
    zero_pool<<<(NG * HD + TB - 1) / TB, TB>>>();
    pool128<<<NN / 200, HD>>>(bufA, batch);
    finalize<<<NG, HD>>>((float*)d_out);
}

// round 7
// speedup vs baseline: 3.7976x; 1.2617x over previous
#include <cuda_runtime.h>
#include <cuda_fp16.h>

#define NN 200000
#define NE 400000
#define NG 64
#define HD 128
#define IND 5
#define TROWS 64
#define SROW 136        // f16 tile row stride (halves): ldmatrix conflict-free
#define LDAF 132        // fp32 staging row stride (floats)
#define GRID_P 304      // persistent CTAs (2 per SM)

// ---------------- device scratch (allocation-free rule) ----------------
__device__ float  g_h5[NN * IND];
__device__ __half g_h[(size_t)NN * HD];     // accumulation base (y + aggr), fp16
__device__ __half g_bufA[(size_t)NN * HD];  // layer outputs ping (fp16)
__device__ __half g_bufB[(size_t)NN * HD];  // layer outputs pong (fp16)
__device__ float  g_pool[NG * HD];
__device__ int    g_cnt[NG];

// ---------------- helpers ----------------
__device__ __forceinline__ unsigned packh2(float a, float b) {
    half2 h = __floats2half2_rn(a, b);
    return *(unsigned*)&h;
}
__device__ __forceinline__ void ldmA(unsigned a[4], unsigned saddr) {
    asm volatile("ldmatrix.sync.aligned.m8n8.x4.shared.b16 {%0,%1,%2,%3}, [%4];"
                 : "=r"(a[0]), "=r"(a[1]), "=r"(a[2]), "=r"(a[3]) : "r"(saddr));
}
__device__ __forceinline__ void mma16(float* d, const unsigned* a, unsigned b0, unsigned b1) {
    asm volatile("mma.sync.aligned.m16n8k16.row.col.f32.f16.f16.f32 "
                 "{%0,%1,%2,%3}, {%4,%5,%6,%7}, {%8,%9}, {%0,%1,%2,%3};"
                 : "+f"(d[0]), "+f"(d[1]), "+f"(d[2]), "+f"(d[3])
                 : "r"(a[0]), "r"(a[1]), "r"(a[2]), "r"(a[3]), "r"(b0), "r"(b1));
}

// ---------------- misc small kernels ----------------
__global__ void copy_f(float* __restrict__ dst, const float* __restrict__ src, int n) {
    int i = blockIdx.x * blockDim.x + threadIdx.x;
    if (i < n) dst[i] = src[i];
}

__global__ void edge5(const int* __restrict__ src, const int* __restrict__ dst,
                      const float* __restrict__ ea,
                      const float* __restrict__ ew, const float* __restrict__ eb,
                      const float* __restrict__ x, float* __restrict__ h) {
    int e = blockIdx.x * blockDim.x + threadIdx.x;
    if (e >= NE) return;
    int s = __ldg(src + e), d = __ldg(dst + e);
    float a = __ldg(ea + e);
#pragma unroll
    for (int j = 0; j < IND; j++) {
        float m = fmaxf(__ldg(x + s * IND + j) + fmaf(a, __ldg(ew + j), __ldg(eb + j)), 0.f);
        atomicAdd(&h[d * IND + j], m);
    }
}

// fp16 edge message + scatter. 16 lanes per edge, 8 halves per lane, v4.f16x2 RED.
__global__ void edge128h(const int* __restrict__ src, const int* __restrict__ dst,
                         const float* __restrict__ ea,
                         const float* __restrict__ ew, const float* __restrict__ eb,
                         const __half* __restrict__ x, __half* __restrict__ h) {
    int t = blockIdx.x * blockDim.x + threadIdx.x;
    int e = t >> 4;
    if (e >= NE) return;
    int lane = t & 15;            // halves [lane*8, lane*8+8)
    int s = __ldg(src + e), d = __ldg(dst + e);
    float a = __ldg(ea + e);
    uint4 xv = __ldg((const uint4*)(x + (size_t)s * HD) + lane);
    float4 w0 = __ldg((const float4*)ew + lane * 2);
    float4 w1 = __ldg((const float4*)ew + lane * 2 + 1);
    float4 c0 = __ldg((const float4*)eb + lane * 2);
    float4 c1 = __ldg((const float4*)eb + lane * 2 + 1);
    float2 x0 = __half22float2(*(half2*)&xv.x);
    float2 x1 = __half22float2(*(half2*)&xv.y);
    float2 x2 = __half22float2(*(half2*)&xv.z);
    float2 x3 = __half22float2(*(half2*)&xv.w);
    unsigned m0 = packh2(fmaxf(x0.x + fmaf(a, w0.x, c0.x), 0.f),
                         fmaxf(x0.y + fmaf(a, w0.y, c0.y), 0.f));
    unsigned m1 = packh2(fmaxf(x1.x + fmaf(a, w0.z, c0.z), 0.f),
                         fmaxf(x1.y + fmaf(a, w0.w, c0.w), 0.f));
    unsigned m2 = packh2(fmaxf(x2.x + fmaf(a, w1.x, c1.x), 0.f),
                         fmaxf(x2.y + fmaf(a, w1.y, c1.y), 0.f));
    unsigned m3 = packh2(fmaxf(x3.x + fmaf(a, w1.z, c1.z), 0.f),
                         fmaxf(x3.y + fmaf(a, w1.w, c1.w), 0.f));
    __half* p = h + (size_t)d * HD + lane * 8;
    asm volatile("red.global.add.noftz.v4.f16x2 [%0], {%1, %2, %3, %4};"
                 :: "l"(p), "r"(m0), "r"(m1), "r"(m2), "r"(m3) : "memory");
}

// ---------------- fused MLP + LN, fp16 m16n8k16, persistent, fp16 I/O ----------------
#define OFF_A   3072
#define OFF_MID 20480
#define OFF_AF  37888
#define SMEM_TOT (OFF_AF + TROWS * LDAF * 4)
#define NTILE (NN / TROWS)

template <int DIN, bool DUAL>
__global__ void __launch_bounds__(256, 2) mlp_tc(
        const void* __restrict__ hin_v,
        const float* __restrict__ w1, const float* __restrict__ b1,
        const float* __restrict__ w2, const float* __restrict__ b2,
        const float* __restrict__ gam, const float* __restrict__ bet,
        __half* __restrict__ out, __half* __restrict__ hdup) {
    extern __shared__ char smem[];
    float* s_b1 = (float*)smem;
    float* s_b2 = s_b1 + 128;
    float* s_g  = s_b1 + 256;
    float* s_bt = s_b1 + 384;
    float* s_mu = s_b1 + 512;
    float* s_rs = s_b1 + 640;
    half*  sA   = (half*)(smem + OFF_A);
    half*  sMid = (half*)(smem + OFF_MID);
    float* sAf  = (float*)(smem + OFF_AF);

    const int tid = threadIdx.x;
    const int w = tid >> 5, lane = tid & 31;
    const int qr = lane >> 2, qc = lane & 3;
    const int wbase = w * 16;
    const int lm_r = ((lane >> 3) & 1) * 8 + (lane & 7);
    const int lm_c = (lane >> 4) * 8;

    if (tid < 128) {
        s_b1[tid] = __ldg(b1 + tid);
        s_b2[tid] = __ldg(b2 + tid);
        s_g[tid]  = __ldg(gam + tid);
        s_bt[tid] = __ldg(bet + tid);
    }

    // ---- W fragments: loaded ONCE per persistent CTA ----
    constexpr int NKS1 = (DIN == HD) ? 8 : 1;
    unsigned wf1[2][NKS1][2], wf2[2][8][2];
#pragma unroll
    for (int nt = 0; nt < 2; nt++) {
        int n = wbase + nt * 8 + qr;
#pragma unroll
        for (int kk = 0; kk < NKS1; kk++) {
            int k0 = kk * 16 + 2 * qc;
            float f0 = (k0 < DIN)     ? __ldg(w1 + (size_t)k0 * HD + n)       : 0.f;
            float f1 = (k0 + 1 < DIN) ? __ldg(w1 + (size_t)(k0 + 1) * HD + n) : 0.f;
            float f2 = (k0 + 8 < DIN) ? __ldg(w1 + (size_t)(k0 + 8) * HD + n) : 0.f;
            float f3 = (k0 + 9 < DIN) ? __ldg(w1 + (size_t)(k0 + 9) * HD + n) : 0.f;
            wf1[nt][kk][0] = packh2(f0, f1);
            wf1[nt][kk][1] = packh2(f2, f3);
        }
#pragma unroll
        for (int kk = 0; kk < 8; kk++) {
            int k0 = kk * 16 + 2 * qc;
            wf2[nt][kk][0] = packh2(__ldg(w2 + (size_t)k0 * HD + n),
                                    __ldg(w2 + (size_t)(k0 + 1) * HD + n));
            wf2[nt][kk][1] = packh2(__ldg(w2 + (size_t)(k0 + 8) * HD + n),
                                    __ldg(w2 + (size_t)(k0 + 9) * HD + n));
        }
    }
    __syncthreads();

    const unsigned sA_base   = (unsigned)__cvta_generic_to_shared(sA);
    const unsigned sMid_base = (unsigned)__cvta_generic_to_shared(sMid);

    for (int tile = blockIdx.x; tile < NTILE; tile += GRID_P) {
        const int n0 = tile * TROWS;

        // ---- A tile -> f16 smem ----
        if (DIN == HD) {
            const __half* hin = (const __half*)hin_v;
            for (int idx = tid; idx < TROWS * 16; idx += 256) {
                int row = idx >> 4, q = idx & 15;
                uint4 v = __ldg((const uint4*)(hin + (size_t)(n0 + row) * HD) + q);
                *(uint4*)(sA + row * SROW + q * 8) = v;
            }
        } else {
            const float* hin = (const float*)hin_v;
            for (int idx = tid; idx < TROWS * 16; idx += 256) {
                int row = idx >> 4, k = idx & 15;
                float f = (k < IND) ? __ldg(hin + (size_t)(n0 + row) * IND + k) : 0.f;
                sA[row * SROW + k] = __float2half_rn(f);
            }
        }
        __syncthreads();

        // ---- GEMM1 + bias1 + ReLU -> sMid (f16) ----
#pragma unroll 1
        for (int mt = 0; mt < TROWS / 16; mt++) {
            float d0[4] = {0, 0, 0, 0}, d1[4] = {0, 0, 0, 0};
            int r0 = mt * 16;
#pragma unroll
            for (int kk = 0; kk < NKS1; kk++) {
                unsigned a[4];
                ldmA(a, sA_base + ((r0 + lm_r) * SROW + kk * 16 + lm_c) * 2);
                mma16(d0, a, wf1[0][kk][0], wf1[0][kk][1]);
                mma16(d1, a, wf1[1][kk][0], wf1[1][kk][1]);
            }
#pragma unroll
            for (int nt = 0; nt < 2; nt++) {
                float* d = nt ? d1 : d0;
                int c0 = wbase + nt * 8 + 2 * qc;
                *(unsigned*)(sMid + (r0 + qr) * SROW + c0) =
                    packh2(fmaxf(d[0] + s_b1[c0], 0.f), fmaxf(d[1] + s_b1[c0 + 1], 0.f));
                *(unsigned*)(sMid + (r0 + 8 + qr) * SROW + c0) =
                    packh2(fmaxf(d[2] + s_b1[c0], 0.f), fmaxf(d[3] + s_b1[c0 + 1], 0.f));
            }
        }
        __syncthreads();

        // ---- GEMM2 + bias2 -> sAf (fp32) ----
#pragma unroll 1
        for (int mt = 0; mt < TROWS / 16; mt++) {
            float d0[4] = {0, 0, 0, 0}, d1[4] = {0, 0, 0, 0};
            int r0 = mt * 16;
#pragma unroll
            for (int kk = 0; kk < 8; kk++) {
                unsigned a[4];
                ldmA(a, sMid_base + ((r0 + lm_r) * SROW + kk * 16 + lm_c) * 2);
                mma16(d0, a, wf2[0][kk][0], wf2[0][kk][1]);
                mma16(d1, a, wf2[1][kk][0], wf2[1][kk][1]);
            }
#pragma unroll
            for (int nt = 0; nt < 2; nt++) {
                float* d = nt ? d1 : d0;
                int c0 = wbase + nt * 8 + 2 * qc;
                *(float2*)(sAf + (r0 + qr) * LDAF + c0) =
                    make_float2(d[0] + s_b2[c0], d[1] + s_b2[c0 + 1]);
                *(float2*)(sAf + (r0 + 8 + qr) * LDAF + c0) =
                    make_float2(d[2] + s_b2[c0], d[3] + s_b2[c0 + 1]);
            }
        }
        __syncthreads();

        // ---- LayerNorm stats: 2 threads per row ----
        if (tid < TROWS * 2) {
            int row = tid >> 1, half_ = tid & 1;
            const float* pr = sAf + row * LDAF + half_ * 64;
            float s = 0.f, s2 = 0.f;
#pragma unroll
            for (int i = 0; i < 16; i++) {
                float4 v = *(const float4*)(pr + i * 4);
                s += v.x + v.y + v.z + v.w;
                s2 += v.x * v.x + v.y * v.y + v.z * v.z + v.w * v.w;
            }
            s  += __shfl_xor_sync(0xffffffffu, s, 1);
            s2 += __shfl_xor_sync(0xffffffffu, s2, 1);
            if (half_ == 0) {
                float mean = s * (1.f / HD);
                float var = s2 * (1.f / HD) - mean * mean;
                s_mu[row] = mean;
                s_rs[row] = rsqrtf(var + 1e-5f);
            }
        }
        __syncthreads();

        // ---- apply LN + ReLU, store fp16 (dual) ----
        for (int idx = tid; idx < TROWS * 32; idx += 256) {
            int row = idx >> 5, q = idx & 31;
            float mean = s_mu[row], rstd = s_rs[row];
            float4 v = *(const float4*)(sAf + row * LDAF + q * 4);
            float o0 = fmaxf((v.x - mean) * rstd * s_g[4 * q + 0] + s_bt[4 * q + 0], 0.f);
            float o1 = fmaxf((v.y - mean) * rstd * s_g[4 * q + 1] + s_bt[4 * q + 1], 0.f);
            float o2 = fmaxf((v.z - mean) * rstd * s_g[4 * q + 2] + s_bt[4 * q + 2], 0.f);
            float o3 = fmaxf((v.w - mean) * rstd * s_g[4 * q + 3] + s_bt[4 * q + 3], 0.f);
            uint2 pk = make_uint2(packh2(o0, o1), packh2(o2, o3));
            size_t off = (size_t)(n0 + row) * HD + 4 * q;
            *(uint2*)(out + off) = pk;
            if (DUAL) *(uint2*)(hdup + off) = pk;
        }
        __syncthreads();
    }
}

// ---------------- pooling ----------------
__global__ void zero_pool() {
    int i = blockIdx.x * blockDim.x + threadIdx.x;
    if (i < NG * HD) g_pool[i] = 0.f;
    if (i < NG) g_cnt[i] = 0;
}

__global__ void pool128(const __half* __restrict__ x, const int* __restrict__ batch) {
    const int CHUNK = 200;
    int n0 = blockIdx.x * CHUNK;
    int n1 = n0 + CHUNK;
    if (n1 > NN) n1 = NN;
    int j = threadIdx.x;
    float acc = 0.f;
    int cnt = 0;
    int cur = batch[n0];
    for (int n = n0; n < n1; n++) {
        int g = batch[n];
        if (g != cur) {
            atomicAdd(&g_pool[cur * HD + j], acc);
            if (j == 0) atomicAdd(&g_cnt[cur], cnt);
            acc = 0.f; cnt = 0; cur = g;
        }
        acc += __half2float(x[(size_t)n * HD + j]);
        cnt++;
    }
    atomicAdd(&g_pool[cur * HD + j], acc);
    if (j == 0) atomicAdd(&g_cnt[cur], cnt);
}

__global__ void finalize(float* __restrict__ out) {
    int g = blockIdx.x, j = threadIdx.x;
    float s = g_pool[g * HD + j];
    int c = g_cnt[g];
    float cf = (float)(c > 1 ? c : 1);
    out[g * 2 * HD + j]      = s / cf;
    out[g * 2 * HD + HD + j] = s;
}

// ---------------------------------------------------------------------------
extern "C" void kernel_launch(void* const* d_in, const int* in_sizes, int n_in,
                              void* d_out, int out_size) {
    const float* x     = (const float*)d_in[0];
    const int*   ei    = (const int*)d_in[1];
    const float* ea    = (const float*)d_in[2];
    const int*   batch = (const int*)d_in[3];
    const float* P[24];
    for (int i = 0; i < 24; i++) P[i] = (const float*)d_in[4 + i];
    const int* esrc = ei;
    const int* edst = ei + NE;

    float* h5;
    __half *h, *bufA, *bufB;
    cudaGetSymbolAddress((void**)&h5, g_h5);
    cudaGetSymbolAddress((void**)&h, g_h);
    cudaGetSymbolAddress((void**)&bufA, g_bufA);
    cudaGetSymbolAddress((void**)&bufB, g_bufB);

    cudaFuncSetAttribute(mlp_tc<IND, true>, cudaFuncAttributeMaxDynamicSharedMemorySize, SMEM_TOT);
    cudaFuncSetAttribute(mlp_tc<HD, true>,  cudaFuncAttributeMaxDynamicSharedMemorySize, SMEM_TOT);
    cudaFuncSetAttribute(mlp_tc<HD, false>, cudaFuncAttributeMaxDynamicSharedMemorySize, SMEM_TOT);

    const int TB = 256;

    // ---- layer 0 (din = 5) ----
    copy_f<<<(NN * IND + TB - 1) / TB, TB>>>(h5, x, NN * IND);
    edge5<<<(NE + TB - 1) / TB, TB>>>(esrc, edst, ea, P[0], P[1], x, h5);
    mlp_tc<IND, true><<<GRID_P, 256, SMEM_TOT>>>(h5, P[2], P[3], P[4], P[5], P[6], P[7], bufA, h);

    // ---- layer 1 ----
    edge128h<<<(NE * 16 + TB - 1) / TB, TB>>>(esrc, edst, ea, P[8], P[9], bufA, h);
    mlp_tc<HD, true><<<GRID_P, 256, SMEM_TOT>>>(h, P[10], P[11], P[12], P[13], P[14], P[15], bufB, h);

    // ---- layer 2 ----
    edge128h<<<(NE * 16 + TB - 1) / TB, TB>>>(esrc, edst, ea, P[16], P[17], bufB, h);
    mlp_tc<HD, false><<<GRID_P, 256, SMEM_TOT>>>(h, P[18], P[19], P[20], P[21], P[22], P[23], bufA, nullptr);

    // ---- pooling ----
    zero_pool<<<(NG * HD + TB - 1) / TB, TB>>>();
    pool128<<<NN / 200, HD>>>(bufA, batch);
    finalize<<<NG, HD>>>((float*)d_out);
}

// round 9
// speedup vs baseline: 4.1670x; 1.0973x over previous
#include <cuda_runtime.h>
#include <cuda_fp16.h>

#define NN 200000
#define NE 400000
#define NG 64
#define HD 128
#define IND 5
#define TROWS 64
#define SROW 136        // f16 tile row stride (halves): ldmatrix conflict-free
#define SPST 12         // partial-sum row stride (floats): 48B, 16B-aligned
#define GRID_P 304      // persistent CTAs (2 per SM)

// ---------------- device scratch (allocation-free rule) ----------------
__device__ float  g_h5[NN * IND];
__device__ __half g_h[(size_t)NN * HD];     // accumulation base (y + aggr), fp16
__device__ __half g_bufA[(size_t)NN * HD];  // layer outputs ping (fp16)
__device__ __half g_bufB[(size_t)NN * HD];  // layer outputs pong (fp16)
__device__ float  g_pool[NG * HD];
__device__ int    g_cnt[NG];

// ---------------- helpers ----------------
__device__ __forceinline__ unsigned packh2(float a, float b) {
    half2 h = __floats2half2_rn(a, b);
    return *(unsigned*)&h;
}
__device__ __forceinline__ void ldmA(unsigned a[4], unsigned saddr) {
    asm volatile("ldmatrix.sync.aligned.m8n8.x4.shared.b16 {%0,%1,%2,%3}, [%4];"
                 : "=r"(a[0]), "=r"(a[1]), "=r"(a[2]), "=r"(a[3]) : "r"(saddr));
}
__device__ __forceinline__ void mma16(float* d, const unsigned* a, unsigned b0, unsigned b1) {
    asm volatile("mma.sync.aligned.m16n8k16.row.col.f32.f16.f16.f32 "
                 "{%0,%1,%2,%3}, {%4,%5,%6,%7}, {%8,%9}, {%0,%1,%2,%3};"
                 : "+f"(d[0]), "+f"(d[1]), "+f"(d[2]), "+f"(d[3])
                 : "r"(a[0]), "r"(a[1]), "r"(a[2]), "r"(a[3]), "r"(b0), "r"(b1));
}

// ---------------- misc small kernels ----------------
__global__ void copy_f(float* __restrict__ dst, const float* __restrict__ src, int n) {
    int i = blockIdx.x * blockDim.x + threadIdx.x;
    if (i < n) dst[i] = src[i];
}

__global__ void edge5(const int* __restrict__ src, const int* __restrict__ dst,
                      const float* __restrict__ ea,
                      const float* __restrict__ ew, const float* __restrict__ eb,
                      const float* __restrict__ x, float* __restrict__ h) {
    int e = blockIdx.x * blockDim.x + threadIdx.x;
    if (e >= NE) return;
    int s = __ldg(src + e), d = __ldg(dst + e);
    float a = __ldg(ea + e);
#pragma unroll
    for (int j = 0; j < IND; j++) {
        float m = fmaxf(__ldg(x + s * IND + j) + fmaf(a, __ldg(ew + j), __ldg(eb + j)), 0.f);
        atomicAdd(&h[d * IND + j], m);
    }
}

// fp16 edge message + scatter. Persistent: lane constants live in registers.
__global__ void edge128h(const int* __restrict__ src, const int* __restrict__ dst,
                         const float* __restrict__ ea,
                         const float* __restrict__ ew, const float* __restrict__ eb,
                         const __half* __restrict__ x, __half* __restrict__ h) {
    const int lane = threadIdx.x & 15;        // halves [lane*8, lane*8+8)
    const int g0 = (blockIdx.x * blockDim.x + threadIdx.x) >> 4;
    const int gs = (gridDim.x * blockDim.x) >> 4;
    const float4 w0 = __ldg((const float4*)ew + lane * 2);
    const float4 w1 = __ldg((const float4*)ew + lane * 2 + 1);
    const float4 c0 = __ldg((const float4*)eb + lane * 2);
    const float4 c1 = __ldg((const float4*)eb + lane * 2 + 1);
    for (int e = g0; e < NE; e += gs) {
        int s = __ldg(src + e), d = __ldg(dst + e);
        float a = __ldg(ea + e);
        uint4 xv = __ldg((const uint4*)(x + (size_t)s * HD) + lane);
        float2 x0 = __half22float2(*(half2*)&xv.x);
        float2 x1 = __half22float2(*(half2*)&xv.y);
        float2 x2 = __half22float2(*(half2*)&xv.z);
        float2 x3 = __half22float2(*(half2*)&xv.w);
        unsigned m0 = packh2(fmaxf(x0.x + fmaf(a, w0.x, c0.x), 0.f),
                             fmaxf(x0.y + fmaf(a, w0.y, c0.y), 0.f));
        unsigned m1 = packh2(fmaxf(x1.x + fmaf(a, w0.z, c0.z), 0.f),
                             fmaxf(x1.y + fmaf(a, w0.w, c0.w), 0.f));
        unsigned m2 = packh2(fmaxf(x2.x + fmaf(a, w1.x, c1.x), 0.f),
                             fmaxf(x2.y + fmaf(a, w1.y, c1.y), 0.f));
        unsigned m3 = packh2(fmaxf(x3.x + fmaf(a, w1.z, c1.z), 0.f),
                             fmaxf(x3.y + fmaf(a, w1.w, c1.w), 0.f));
        __half* p = h + (size_t)d * HD + lane * 8;
        asm volatile("red.global.add.noftz.v4.f16x2 [%0], {%1, %2, %3, %4};"
                     :: "l"(p), "r"(m0), "r"(m1), "r"(m2), "r"(m3) : "memory");
    }
}

// ---------------- fused MLP + LN, fp16 m16n8k16, persistent, fp16 I/O ----------------
// smem (bytes): [0,3072) params | sA f16 64xSROW | sMid f16 64xSROW | sp fp32 2x64xSPST
#define OFF_A   3072
#define OFF_MID (OFF_A + TROWS * SROW * 2)
#define OFF_SP  (OFF_MID + TROWS * SROW * 2)
#define SMEM_TOT (OFF_SP + 2 * TROWS * SPST * 4)
#define NTILE (NN / TROWS)

template <int DIN, bool DUAL>
__global__ void __launch_bounds__(256, 2) mlp_tc(
        const void* __restrict__ hin_v,
        const float* __restrict__ w1, const float* __restrict__ b1,
        const float* __restrict__ w2, const float* __restrict__ b2,
        const float* __restrict__ gam, const float* __restrict__ bet,
        __half* __restrict__ out, __half* __restrict__ hdup) {
    extern __shared__ char smem[];
    float* s_b1 = (float*)smem;
    float* s_b2 = s_b1 + 128;
    float* s_g  = s_b1 + 256;
    float* s_bt = s_b1 + 384;
    half*  sA   = (half*)(smem + OFF_A);
    half*  sMid = (half*)(smem + OFF_MID);
    float* sp_s = (float*)(smem + OFF_SP);          // [64][SPST] row sums (8 used)
    float* sp_q = sp_s + TROWS * SPST;              // [64][SPST] row sumsq

    const int tid = threadIdx.x;
    const int w = tid >> 5, lane = tid & 31;
    const int qr = lane >> 2, qc = lane & 3;
    const int wbase = w * 16;
    const int lm_r = ((lane >> 3) & 1) * 8 + (lane & 7);
    const int lm_c = (lane >> 4) * 8;

    if (tid < 128) {
        s_b1[tid] = __ldg(b1 + tid);
        s_b2[tid] = __ldg(b2 + tid);
        s_g[tid]  = __ldg(gam + tid);
        s_bt[tid] = __ldg(bet + tid);
    }

    // ---- W fragments: loaded ONCE per persistent CTA ----
    constexpr int NKS1 = (DIN == HD) ? 8 : 1;
    unsigned wf1[2][NKS1][2], wf2[2][8][2];
#pragma unroll
    for (int nt = 0; nt < 2; nt++) {
        int n = wbase + nt * 8 + qr;
#pragma unroll
        for (int kk = 0; kk < NKS1; kk++) {
            int k0 = kk * 16 + 2 * qc;
            float f0 = (k0 < DIN)     ? __ldg(w1 + (size_t)k0 * HD + n)       : 0.f;
            float f1 = (k0 + 1 < DIN) ? __ldg(w1 + (size_t)(k0 + 1) * HD + n) : 0.f;
            float f2 = (k0 + 8 < DIN) ? __ldg(w1 + (size_t)(k0 + 8) * HD + n) : 0.f;
            float f3 = (k0 + 9 < DIN) ? __ldg(w1 + (size_t)(k0 + 9) * HD + n) : 0.f;
            wf1[nt][kk][0] = packh2(f0, f1);
            wf1[nt][kk][1] = packh2(f2, f3);
        }
#pragma unroll
        for (int kk = 0; kk < 8; kk++) {
            int k0 = kk * 16 + 2 * qc;
            wf2[nt][kk][0] = packh2(__ldg(w2 + (size_t)k0 * HD + n),
                                    __ldg(w2 + (size_t)(k0 + 1) * HD + n));
            wf2[nt][kk][1] = packh2(__ldg(w2 + (size_t)(k0 + 8) * HD + n),
                                    __ldg(w2 + (size_t)(k0 + 9) * HD + n));
        }
    }
    __syncthreads();

    const unsigned sA_base   = (unsigned)__cvta_generic_to_shared(sA);
    const unsigned sMid_base = (unsigned)__cvta_generic_to_shared(sMid);

    for (int tile = blockIdx.x; tile < NTILE; tile += GRID_P) {
        const int n0 = tile * TROWS;

        // ---- A tile -> f16 smem ----
        if (DIN == HD) {
            const __half* hin = (const __half*)hin_v;
            for (int idx = tid; idx < TROWS * 16; idx += 256) {
                int row = idx >> 4, q = idx & 15;
                uint4 v = __ldg((const uint4*)(hin + (size_t)(n0 + row) * HD) + q);
                *(uint4*)(sA + row * SROW + q * 8) = v;
            }
        } else {
            const float* hin = (const float*)hin_v;
            for (int idx = tid; idx < TROWS * 16; idx += 256) {
                int row = idx >> 4, k = idx & 15;
                float f = (k < IND) ? __ldg(hin + (size_t)(n0 + row) * IND + k) : 0.f;
                sA[row * SROW + k] = __float2half_rn(f);
            }
        }
        __syncthreads();

        // ---- GEMM1 + bias1 + ReLU -> sMid (f16) ----
#pragma unroll 1
        for (int mt = 0; mt < TROWS / 16; mt++) {
            float d0[4] = {0, 0, 0, 0}, d1[4] = {0, 0, 0, 0};
            int r0 = mt * 16;
#pragma unroll
            for (int kk = 0; kk < NKS1; kk++) {
                unsigned a[4];
                ldmA(a, sA_base + ((r0 + lm_r) * SROW + kk * 16 + lm_c) * 2);
                mma16(d0, a, wf1[0][kk][0], wf1[0][kk][1]);
                mma16(d1, a, wf1[1][kk][0], wf1[1][kk][1]);
            }
#pragma unroll
            for (int nt = 0; nt < 2; nt++) {
                float* d = nt ? d1 : d0;
                int c0 = wbase + nt * 8 + 2 * qc;
                *(unsigned*)(sMid + (r0 + qr) * SROW + c0) =
                    packh2(fmaxf(d[0] + s_b1[c0], 0.f), fmaxf(d[1] + s_b1[c0 + 1], 0.f));
                *(unsigned*)(sMid + (r0 + 8 + qr) * SROW + c0) =
                    packh2(fmaxf(d[2] + s_b1[c0], 0.f), fmaxf(d[3] + s_b1[c0 + 1], 0.f));
            }
        }
        __syncthreads();

        // ---- GEMM2 + bias2: partial LN sums -> sp, fp16 values -> sA ----
#pragma unroll 1
        for (int mt = 0; mt < TROWS / 16; mt++) {
            float d0[4] = {0, 0, 0, 0}, d1[4] = {0, 0, 0, 0};
            int r0 = mt * 16;
#pragma unroll
            for (int kk = 0; kk < 8; kk++) {
                unsigned a[4];
                ldmA(a, sMid_base + ((r0 + lm_r) * SROW + kk * 16 + lm_c) * 2);
                mma16(d0, a, wf2[0][kk][0], wf2[0][kk][1]);
                mma16(d1, a, wf2[1][kk][0], wf2[1][kk][1]);
            }
            // bias
            {
                int c0 = wbase + 2 * qc, c1 = wbase + 8 + 2 * qc;
                d0[0] += s_b2[c0]; d0[1] += s_b2[c0 + 1];
                d0[2] += s_b2[c0]; d0[3] += s_b2[c0 + 1];
                d1[0] += s_b2[c1]; d1[1] += s_b2[c1 + 1];
                d1[2] += s_b2[c1]; d1[3] += s_b2[c1 + 1];
            }
            // per-row partial sums over this warp's 4 cols (rows r0+qr, r0+qr+8)
            float sa = d0[0] + d0[1] + d1[0] + d1[1];
            float sb = d0[2] + d0[3] + d1[2] + d1[3];
            float qa = d0[0] * d0[0] + d0[1] * d0[1] + d1[0] * d1[0] + d1[1] * d1[1];
            float qb = d0[2] * d0[2] + d0[3] * d0[3] + d1[2] * d1[2] + d1[3] * d1[3];
#pragma unroll
            for (int o = 1; o <= 2; o <<= 1) {
                sa += __shfl_xor_sync(0xffffffffu, sa, o);
                sb += __shfl_xor_sync(0xffffffffu, sb, o);
                qa += __shfl_xor_sync(0xffffffffu, qa, o);
                qb += __shfl_xor_sync(0xffffffffu, qb, o);
            }
            if (qc == 0) {
                sp_s[(r0 + qr) * SPST + w] = sa;
                sp_s[(r0 + 8 + qr) * SPST + w] = sb;
                sp_q[(r0 + qr) * SPST + w] = qa;
                sp_q[(r0 + 8 + qr) * SPST + w] = qb;
            }
            // stash biased values as fp16 into sA (free after GEMM1)
            {
                int c0 = wbase + 2 * qc;
                *(unsigned*)(sA + (r0 + qr) * SROW + c0)      = packh2(d0[0], d0[1]);
                *(unsigned*)(sA + (r0 + qr) * SROW + c0 + 8)  = packh2(d1[0], d1[1]);
                *(unsigned*)(sA + (r0 + 8 + qr) * SROW + c0)     = packh2(d0[2], d0[3]);
                *(unsigned*)(sA + (r0 + 8 + qr) * SROW + c0 + 8) = packh2(d1[2], d1[3]);
            }
        }
        __syncthreads();

        // ---- LN apply + ReLU + coalesced fp16 store ----
        for (int idx = tid; idx < TROWS * 16; idx += 256) {
            int row = idx >> 4, q = idx & 15;
            // row stats from 8 warp partials (SPST=12 keeps float4 loads 16B-aligned)
            float4 sa = *(const float4*)(sp_s + row * SPST);
            float4 sb = *(const float4*)(sp_s + row * SPST + 4);
            float4 qa = *(const float4*)(sp_q + row * SPST);
            float4 qb = *(const float4*)(sp_q + row * SPST + 4);
            float s  = sa.x + sa.y + sa.z + sa.w + sb.x + sb.y + sb.z + sb.w;
            float s2 = qa.x + qa.y + qa.z + qa.w + qb.x + qb.y + qb.z + qb.w;
            float mean = s * (1.f / HD);
            float var = s2 * (1.f / HD) - mean * mean;
            float rstd = rsqrtf(var + 1e-5f);
            uint4 v = *(const uint4*)(sA + row * SROW + q * 8);
            float2 v0 = __half22float2(*(half2*)&v.x);
            float2 v1 = __half22float2(*(half2*)&v.y);
            float2 v2 = __half22float2(*(half2*)&v.z);
            float2 v3 = __half22float2(*(half2*)&v.w);
            int c = q * 8;
            uint4 o;
            o.x = packh2(fmaxf((v0.x - mean) * rstd * s_g[c + 0] + s_bt[c + 0], 0.f),
                         fmaxf((v0.y - mean) * rstd * s_g[c + 1] + s_bt[c + 1], 0.f));
            o.y = packh2(fmaxf((v1.x - mean) * rstd * s_g[c + 2] + s_bt[c + 2], 0.f),
                         fmaxf((v1.y - mean) * rstd * s_g[c + 3] + s_bt[c + 3], 0.f));
            o.z = packh2(fmaxf((v2.x - mean) * rstd * s_g[c + 4] + s_bt[c + 4], 0.f),
                         fmaxf((v2.y - mean) * rstd * s_g[c + 5] + s_bt[c + 5], 0.f));
            o.w = packh2(fmaxf((v3.x - mean) * rstd * s_g[c + 6] + s_bt[c + 6], 0.f),
                         fmaxf((v3.y - mean) * rstd * s_g[c + 7] + s_bt[c + 7], 0.f));
            size_t off = (size_t)(n0 + row) * HD + c;
            *(uint4*)(out + off) = o;
            if (DUAL) *(uint4*)(hdup + off) = o;
        }
        __syncthreads();
    }
}

// ---------------- pooling ----------------
__global__ void zero_pool() {
    int i = blockIdx.x * blockDim.x + threadIdx.x;
    if (i < NG * HD) g_pool[i] = 0.f;
    if (i < NG) g_cnt[i] = 0;
}

__global__ void pool128(const __half* __restrict__ x, const int* __restrict__ batch) {
    const int CHUNK = 50;                   // 4000 blocks
    int n0 = blockIdx.x * CHUNK;
    int n1 = n0 + CHUNK;
    if (n1 > NN) n1 = NN;
    int j = threadIdx.x;
    float acc = 0.f;
    int cnt = 0;
    int cur = batch[n0];
    for (int n = n0; n < n1; n++) {
        int g = batch[n];
        if (g != cur) {
            atomicAdd(&g_pool[cur * HD + j], acc);
            if (j == 0) atomicAdd(&g_cnt[cur], cnt);
            acc = 0.f; cnt = 0; cur = g;
        }
        acc += __half2float(x[(size_t)n * HD + j]);
        cnt++;
    }
    atomicAdd(&g_pool[cur * HD + j], acc);
    if (j == 0) atomicAdd(&g_cnt[cur], cnt);
}

__global__ void finalize(float* __restrict__ out) {
    int g = blockIdx.x, j = threadIdx.x;
    float s = g_pool[g * HD + j];
    int c = g_cnt[g];
    float cf = (float)(c > 1 ? c : 1);
    out[g * 2 * HD + j]      = s / cf;
    out[g * 2 * HD + HD + j] = s;
}

// ---------------------------------------------------------------------------
extern "C" void kernel_launch(void* const* d_in, const int* in_sizes, int n_in,
                              void* d_out, int out_size) {
    const float* x     = (const float*)d_in[0];
    const int*   ei    = (const int*)d_in[1];
    const float* ea    = (const float*)d_in[2];
    const int*   batch = (const int*)d_in[3];
    const float* P[24];
    for (int i = 0; i < 24; i++) P[i] = (const float*)d_in[4 + i];
    const int* esrc = ei;
    const int* edst = ei + NE;

    float* h5;
    __half *h, *bufA, *bufB;
    cudaGetSymbolAddress((void**)&h5, g_h5);
    cudaGetSymbolAddress((void**)&h, g_h);
    cudaGetSymbolAddress((void**)&bufA, g_bufA);
    cudaGetSymbolAddress((void**)&bufB, g_bufB);

    cudaFuncSetAttribute(mlp_tc<IND, true>, cudaFuncAttributeMaxDynamicSharedMemorySize, SMEM_TOT);
    cudaFuncSetAttribute(mlp_tc<HD, true>,  cudaFuncAttributeMaxDynamicSharedMemorySize, SMEM_TOT);
    cudaFuncSetAttribute(mlp_tc<HD, false>, cudaFuncAttributeMaxDynamicSharedMemorySize, SMEM_TOT);

    const int TB = 256;
    const int GEDGE = 3125;   // 3125*256/16 = 50000 edge slots, 8 iters

    // ---- layer 0 (din = 5) ----
    copy_f<<<(NN * IND + TB - 1) / TB, TB>>>(h5, x, NN * IND);
    edge5<<<(NE + TB - 1) / TB, TB>>>(esrc, edst, ea, P[0], P[1], x, h5);
    mlp_tc<IND, true><<<GRID_P, 256, SMEM_TOT>>>(h5, P[2], P[3], P[4], P[5], P[6], P[7], bufA, h);

    // ---- layer 1 ----
    edge128h<<<GEDGE, TB>>>(esrc, edst, ea, P[8], P[9], bufA, h);
    mlp_tc<HD, true><<<GRID_P, 256, SMEM_TOT>>>(h, P[10], P[11], P[12], P[13], P[14], P[15], bufB, h);

    // ---- layer 2 ----
    edge128h<<<GEDGE, TB>>>(esrc, edst, ea, P[16], P[17], bufB, h);
    mlp_tc<HD, false><<<GRID_P, 256, SMEM_TOT>>>(h, P[18], P[19], P[20], P[21], P[22], P[23], bufA, nullptr);

    // ---- pooling ----
    zero_pool<<<(NG * HD + TB - 1) / TB, TB>>>();
    pool128<<<NN / 50, HD>>>(bufA, batch);
    finalize<<<NG, HD>>>((float*)d_out);
}